// round 2
// baseline (speedup 1.0000x reference)
#include <cuda_runtime.h>
#include <math.h>

// Problem constants (from reference)
#define N0c  1982464
#define N1c  123904
#define N2c  11264
#define N3c  1024
#define E0c  1858560
#define E1c  112640
#define E2c  10240
#define DIN  128
#define DH   256
#define DOUT 47

// ---------------- scratch (device globals; no allocations allowed) ----------
__device__ float g_agg0[(size_t)N1c * DIN];   // 63.4 MB
__device__ float g_cnt0[N1c];
__device__ float g_h1[(size_t)N1c * DH];      // 126.9 MB
__device__ float g_agg1[(size_t)N2c * DH];    // 11.5 MB
__device__ float g_cnt1[N2c];
__device__ float g_h2[(size_t)N2c * DH];      // 11.5 MB
__device__ float g_agg2[(size_t)N3c * DH];    // 1.0 MB
__device__ float g_cnt2[N3c];

// ---------------- zero ------------------------------------------------------
__global__ void zero_agg(float4* agg4, float* cnt, int n4, int ncnt) {
    int i = blockIdx.x * blockDim.x + threadIdx.x;
    if (i < n4)   agg4[i] = make_float4(0.f, 0.f, 0.f, 0.f);
    if (i < ncnt) cnt[i]  = 0.f;
}

// ---------------- scatter: one warp per edge --------------------------------
__device__ __forceinline__ void red_v4(float* p, float4 v) {
    asm volatile("red.global.add.v4.f32 [%0], {%1,%2,%3,%4};"
                 :: "l"(p), "f"(v.x), "f"(v.y), "f"(v.z), "f"(v.w) : "memory");
}

// D = 128 feature dims: 1 float4 per lane
__global__ void scatter_x(const int* __restrict__ src, const int* __restrict__ dst,
                          const float* __restrict__ x, float* __restrict__ agg,
                          float* __restrict__ cnt, int E) {
    int e    = (blockIdx.x * blockDim.x + threadIdx.x) >> 5;
    int lane = threadIdx.x & 31;
    if (e >= E) return;
    int s = src[e], d = dst[e];
    const float4* xr = (const float4*)(x + (size_t)s * DIN);
    float4 v = xr[lane];
    red_v4(agg + (size_t)d * DIN + lane * 4, v);
    if (lane == 0)
        atomicAdd(cnt + d, 1.0f);
}

// D = 256 feature dims: 2 float4 per lane
__global__ void scatter_h(const int* __restrict__ src, const int* __restrict__ dst,
                          const float* __restrict__ h, float* __restrict__ agg,
                          float* __restrict__ cnt, int E) {
    int e    = (blockIdx.x * blockDim.x + threadIdx.x) >> 5;
    int lane = threadIdx.x & 31;
    if (e >= E) return;
    int s = src[e], d = dst[e];
    const float4* hr = (const float4*)(h + (size_t)s * DH);
    float4 v0 = hr[lane];
    float4 v1 = hr[lane + 32];
    red_v4(agg + (size_t)d * DH + lane * 4,        v0);
    red_v4(agg + (size_t)d * DH + (lane + 32) * 4, v1);
    if (lane == 0)
        atomicAdd(cnt + d, 1.0f);
}

// ---------------- normalize: agg /= max(cnt,1) ------------------------------
__global__ void normalize_k(float4* agg4, const float* __restrict__ cnt,
                            int cols4, int total4) {
    int i = blockIdx.x * blockDim.x + threadIdx.x;
    if (i >= total4) return;
    int row = i / cols4;
    float s = 1.0f / fmaxf(cnt[row], 1.0f);
    float4 v = agg4[i];
    v.x *= s; v.y *= s; v.z *= s; v.w *= s;
    agg4[i] = v;
}

// ---------------- SAGE layer GEMM: C = relu(A1@Wl + A2@Wr + b) --------------
// A1: [M, KA] (normalized agg), A2: [M, KB] (self feats),
// Wl: [KA, 256], Wr: [KB, 256] row-major. C: [M, 256].
// Tiles: BM=64, BN=64, BK=16; 256 threads; 4x4 register tile per thread.
template<int KA, int KB>
__global__ void __launch_bounds__(256)
sage_gemm(const float* __restrict__ A1, const float* __restrict__ A2,
          const float* __restrict__ Wl, const float* __restrict__ Wr,
          const float* __restrict__ bias, float* __restrict__ C,
          int M, int doRelu)
{
    const int BK = 16;
    __shared__ float As[BK][68];   // pad 4: keeps 16B alignment, reduces conflicts
    __shared__ float Bs[BK][68];

    int tid     = threadIdx.x;
    int rowBase = blockIdx.x * 64;
    int colBase = blockIdx.y * 64;

    int ty = tid >> 4;          // 0..15 -> output rows ty*4..ty*4+3
    int tx = tid & 15;          // 0..15 -> output cols tx*4..tx*4+3

    int aRow = tid >> 2;        // 0..63
    int aK4  = (tid & 3) * 4;   // 0,4,8,12
    int bK   = tid >> 4;        // 0..15
    int bC4  = (tid & 15) * 4;  // 0..60

    float acc[4][4];
#pragma unroll
    for (int i = 0; i < 4; i++)
#pragma unroll
        for (int j = 0; j < 4; j++) acc[i][j] = 0.f;

    const int K = KA + KB;
    for (int k0 = 0; k0 < K; k0 += BK) {
        // ---- load A tile (transposed to As[k][m]) ----
        const float* Arow;
        int kk;
        if (k0 < KA) { Arow = A1 + (size_t)(rowBase + aRow) * KA; kk = k0 + aK4; }
        else         { Arow = A2 + (size_t)(rowBase + aRow) * KB; kk = k0 - KA + aK4; }
        float4 av = *(const float4*)(Arow + kk);
        As[aK4 + 0][aRow] = av.x;
        As[aK4 + 1][aRow] = av.y;
        As[aK4 + 2][aRow] = av.z;
        As[aK4 + 3][aRow] = av.w;

        // ---- load W tile ----
        const float* Wrow;
        if (k0 < KA) Wrow = Wl + (size_t)(k0 + bK) * DH;
        else         Wrow = Wr + (size_t)(k0 - KA + bK) * DH;
        float4 bv = *(const float4*)(Wrow + colBase + bC4);
        *(float4*)&Bs[bK][bC4] = bv;

        __syncthreads();
#pragma unroll
        for (int k = 0; k < BK; ++k) {
            float4 a = *(const float4*)&As[k][ty * 4];
            float4 b = *(const float4*)&Bs[k][tx * 4];
            acc[0][0] += a.x * b.x; acc[0][1] += a.x * b.y; acc[0][2] += a.x * b.z; acc[0][3] += a.x * b.w;
            acc[1][0] += a.y * b.x; acc[1][1] += a.y * b.y; acc[1][2] += a.y * b.z; acc[1][3] += a.y * b.w;
            acc[2][0] += a.z * b.x; acc[2][1] += a.z * b.y; acc[2][2] += a.z * b.z; acc[2][3] += a.z * b.w;
            acc[3][0] += a.w * b.x; acc[3][1] += a.w * b.y; acc[3][2] += a.w * b.z; acc[3][3] += a.w * b.w;
        }
        __syncthreads();
    }

    float4 bb = *(const float4*)(bias + colBase + tx * 4);
#pragma unroll
    for (int i = 0; i < 4; i++) {
        int r = rowBase + ty * 4 + i;
        float4 o;
        o.x = acc[i][0] + bb.x;
        o.y = acc[i][1] + bb.y;
        o.z = acc[i][2] + bb.z;
        o.w = acc[i][3] + bb.w;
        if (doRelu) {
            o.x = fmaxf(o.x, 0.f); o.y = fmaxf(o.y, 0.f);
            o.z = fmaxf(o.z, 0.f); o.w = fmaxf(o.w, 0.f);
        }
        *(float4*)(C + (size_t)r * DH + colBase + tx * 4) = o;
    }
}

// ---------------- final layer: [1024 x 47] logits + log_softmax -------------
// One block per target row. K = 256(agg) + 256(self).
__global__ void __launch_bounds__(64)
final_layer(const float* __restrict__ agg, const float* __restrict__ h,
            const float* __restrict__ Wl, const float* __restrict__ Wr,
            const float* __restrict__ bias, float* __restrict__ out)
{
    __shared__ float sA[DH];
    __shared__ float sH[DH];
    __shared__ float sL[DOUT];
    __shared__ float sRed[2];

    int row = blockIdx.x;
    int tid = threadIdx.x;

    for (int i = tid; i < DH; i += 64) {
        sA[i] = agg[(size_t)row * DH + i];
        sH[i] = h[(size_t)row * DH + i];
    }
    __syncthreads();

    if (tid < DOUT) {
        float accv = bias[tid];
#pragma unroll 8
        for (int k = 0; k < DH; ++k) accv += sA[k] * Wl[k * DOUT + tid];
#pragma unroll 8
        for (int k = 0; k < DH; ++k) accv += sH[k] * Wr[k * DOUT + tid];
        sL[tid] = accv;
    }
    __syncthreads();

    if (tid < 32) {
        float v1 = (tid < DOUT)      ? sL[tid]      : -INFINITY;
        float v2 = (tid + 32 < DOUT) ? sL[tid + 32] : -INFINITY;
        float m = fmaxf(v1, v2);
#pragma unroll
        for (int off = 16; off > 0; off >>= 1)
            m = fmaxf(m, __shfl_xor_sync(0xffffffffu, m, off));
        float s = ((tid < DOUT)      ? expf(v1 - m) : 0.f)
                + ((tid + 32 < DOUT) ? expf(v2 - m) : 0.f);
#pragma unroll
        for (int off = 16; off > 0; off >>= 1)
            s += __shfl_xor_sync(0xffffffffu, s, off);
        if (tid == 0) { sRed[0] = m; sRed[1] = logf(s); }
    }
    __syncthreads();

    if (tid < DOUT)
        out[(size_t)row * DOUT + tid] = sL[tid] - sRed[0] - sRed[1];
}

// ---------------- launch ----------------------------------------------------
extern "C" void kernel_launch(void* const* d_in, const int* in_sizes, int n_in,
                              void* d_out, int out_size) {
    const float* x   = (const float*)d_in[0];
    const float* Wl0 = (const float*)d_in[1];
    const float* Wr0 = (const float*)d_in[2];
    const float* b0  = (const float*)d_in[3];
    const float* Wl1 = (const float*)d_in[4];
    const float* Wr1 = (const float*)d_in[5];
    const float* b1  = (const float*)d_in[6];
    const float* Wl2 = (const float*)d_in[7];
    const float* Wr2 = (const float*)d_in[8];
    const float* b2  = (const float*)d_in[9];
    const int* src0  = (const int*)d_in[10];
    const int* dst0  = (const int*)d_in[11];
    const int* src1  = (const int*)d_in[12];
    const int* dst1  = (const int*)d_in[13];
    const int* src2  = (const int*)d_in[14];
    const int* dst2  = (const int*)d_in[15];
    float* out = (float*)d_out;

    float *agg0, *cnt0, *h1, *agg1, *cnt1, *h2, *agg2, *cnt2;
    cudaGetSymbolAddress((void**)&agg0, g_agg0);
    cudaGetSymbolAddress((void**)&cnt0, g_cnt0);
    cudaGetSymbolAddress((void**)&h1,   g_h1);
    cudaGetSymbolAddress((void**)&agg1, g_agg1);
    cudaGetSymbolAddress((void**)&cnt1, g_cnt1);
    cudaGetSymbolAddress((void**)&h2,   g_h2);
    cudaGetSymbolAddress((void**)&agg2, g_agg2);
    cudaGetSymbolAddress((void**)&cnt2, g_cnt2);

    // ---- layer 0 ----
    zero_agg<<<(N1c * (DIN/4) + 255) / 256, 256>>>((float4*)agg0, cnt0, N1c * (DIN/4), N1c);
    scatter_x<<<E0c / 8, 256>>>(src0, dst0, x, agg0, cnt0, E0c);
    normalize_k<<<(N1c * (DIN/4) + 255) / 256, 256>>>((float4*)agg0, cnt0, DIN/4, N1c * (DIN/4));
    sage_gemm<DIN, DIN><<<dim3(N1c / 64, 4), 256>>>(agg0, x, Wl0, Wr0, b0, h1, N1c, 1);

    // ---- layer 1 ----
    zero_agg<<<(N2c * (DH/4) + 255) / 256, 256>>>((float4*)agg1, cnt1, N2c * (DH/4), N2c);
    scatter_h<<<E1c / 8, 256>>>(src1, dst1, h1, agg1, cnt1, E1c);
    normalize_k<<<(N2c * (DH/4) + 255) / 256, 256>>>((float4*)agg1, cnt1, DH/4, N2c * (DH/4));
    sage_gemm<DH, DH><<<dim3(N2c / 64, 4), 256>>>(agg1, h1, Wl1, Wr1, b1, h2, N2c, 1);

    // ---- layer 2 ----
    zero_agg<<<(N3c * (DH/4) + 255) / 256, 256>>>((float4*)agg2, cnt2, N3c * (DH/4), N3c);
    scatter_h<<<E2c / 8, 256>>>(src2, dst2, h2, agg2, cnt2, E2c);
    normalize_k<<<(N3c * (DH/4) + 255) / 256, 256>>>((float4*)agg2, cnt2, DH/4, N3c * (DH/4));
    final_layer<<<N3c, 64>>>(agg2, h2, Wl2, Wr2, b2, out);
}

// round 3
// speedup vs baseline: 1.0139x; 1.0139x over previous
#include <cuda_runtime.h>
#include <math.h>

// Problem constants (from reference)
#define N0c  1982464
#define N1c  123904
#define N2c  11264
#define N3c  1024
#define E0c  1858560
#define E1c  112640
#define E2c  10240
#define DIN  128
#define DH   256
#define DOUT 47

// ---------------- scratch (device globals; no allocations allowed) ----------
__device__ float g_agg0[(size_t)N1c * DIN];   // 63.4 MB (unnormalized sums)
__device__ float g_cnt0[N1c];
__device__ float g_h1[(size_t)N1c * DH];      // 126.9 MB
__device__ float g_agg1[(size_t)N2c * DH];    // 11.5 MB
__device__ float g_cnt1[N2c];
__device__ float g_h2[(size_t)N2c * DH];      // 11.5 MB
__device__ float g_agg2[(size_t)N3c * DH];    // 1.0 MB
__device__ float g_cnt2[N3c];

// ---------------- zero ------------------------------------------------------
__global__ void zero_agg(float4* agg4, float* cnt, int n4, int ncnt) {
    int i = blockIdx.x * blockDim.x + threadIdx.x;
    if (i < n4)   agg4[i] = make_float4(0.f, 0.f, 0.f, 0.f);
    if (i < ncnt) cnt[i]  = 0.f;
}

// ---------------- scatter: one warp per edge --------------------------------
__device__ __forceinline__ void red_v4(float* p, float4 v) {
    asm volatile("red.global.add.v4.f32 [%0], {%1,%2,%3,%4};"
                 :: "l"(p), "f"(v.x), "f"(v.y), "f"(v.z), "f"(v.w) : "memory");
}

// D = 128 feature dims: 1 float4 per lane
__global__ void scatter_x(const int* __restrict__ src, const int* __restrict__ dst,
                          const float* __restrict__ x, float* __restrict__ agg,
                          float* __restrict__ cnt, int E) {
    int e    = (blockIdx.x * blockDim.x + threadIdx.x) >> 5;
    int lane = threadIdx.x & 31;
    if (e >= E) return;
    int s = src[e], d = dst[e];
    const float4* xr = (const float4*)(x + (size_t)s * DIN);
    float4 v = xr[lane];
    red_v4(agg + (size_t)d * DIN + lane * 4, v);
    if (lane == 0)
        atomicAdd(cnt + d, 1.0f);
}

// D = 256 feature dims: 2 float4 per lane
__global__ void scatter_h(const int* __restrict__ src, const int* __restrict__ dst,
                          const float* __restrict__ h, float* __restrict__ agg,
                          float* __restrict__ cnt, int E) {
    int e    = (blockIdx.x * blockDim.x + threadIdx.x) >> 5;
    int lane = threadIdx.x & 31;
    if (e >= E) return;
    int s = src[e], d = dst[e];
    const float4* hr = (const float4*)(h + (size_t)s * DH);
    float4 v0 = hr[lane];
    float4 v1 = hr[lane + 32];
    red_v4(agg + (size_t)d * DH + lane * 4,        v0);
    red_v4(agg + (size_t)d * DH + (lane + 32) * 4, v1);
    if (lane == 0)
        atomicAdd(cnt + d, 1.0f);
}

// ---------------- f32x2 packed-FMA SAGE GEMM --------------------------------
// C = relu( (A1/cnt) @ Wl + A2 @ Wr + b ),  Wl:[KA,256], Wr:[KB,256], C:[M,256]
// BM=BN=128, BK=16, 256 threads, 8x8 per thread.
// Accumulators packed in pairs along M => A operand is natural 64-bit pairs
// straight from shared memory; B operand splatted via mov.b64 {r,r}.
template<int KA, int KB>
__global__ void __launch_bounds__(256)
sage_gemm2(const float* __restrict__ A1, const float* __restrict__ cnt,
           const float* __restrict__ A2,
           const float* __restrict__ Wl, const float* __restrict__ Wr,
           const float* __restrict__ bias, float* __restrict__ C,
           int doRelu)
{
    const int BK = 16;
    __shared__ float As[BK][132];   // [k][m], padded row = 528B (16B aligned)
    __shared__ float Bs[BK][132];   // [k][n]

    int tid     = threadIdx.x;
    int rowBase = blockIdx.x * 128;
    int colBase = blockIdx.y * 128;

    int ty = tid >> 4;            // 0..15 -> rows ty*8 .. ty*8+7
    int tx = tid & 15;            // 0..15 -> cols tx*8 .. tx*8+7

    // A-tile load mapping: 128 rows x 16 k, 256 threads x 2 quads
    int aRow = tid & 127;
    int aKq  = (tid >> 7) * 4;    // 0 or 4; second quad at +8

    // B-tile load mapping: 16 k x 128 n
    int bK = tid >> 4;            // 0..15
    int bC = (tid & 15) * 8;      // 0..120

    // mean-normalization scale for this thread's A rows (fused normalize)
    float scaleA = 1.0f / fmaxf(cnt[rowBase + aRow], 1.0f);

    unsigned long long acc2[4][8];
#pragma unroll
    for (int i = 0; i < 4; i++)
#pragma unroll
        for (int j = 0; j < 8; j++) acc2[i][j] = 0ULL;

    const int K = KA + KB;
    for (int k0 = 0; k0 < K; k0 += BK) {
        bool fromA1 = (k0 < KA);
        // ---- A tile (transposed into As[k][m], scaled if from agg) ----
        const float* Abase = fromA1
            ? A1 + (size_t)(rowBase + aRow) * KA + k0
            : A2 + (size_t)(rowBase + aRow) * KB + (k0 - KA);
        float sc = fromA1 ? scaleA : 1.0f;
#pragma unroll
        for (int q = 0; q < 2; q++) {
            int kk = aKq + q * 8;
            float4 v = *(const float4*)(Abase + kk);
            As[kk + 0][aRow] = v.x * sc;
            As[kk + 1][aRow] = v.y * sc;
            As[kk + 2][aRow] = v.z * sc;
            As[kk + 3][aRow] = v.w * sc;
        }
        // ---- B tile ----
        const float* Wrow = fromA1
            ? Wl + (size_t)(k0 + bK) * DH
            : Wr + (size_t)(k0 - KA + bK) * DH;
        *(float4*)&Bs[bK][bC]     = *(const float4*)(Wrow + colBase + bC);
        *(float4*)&Bs[bK][bC + 4] = *(const float4*)(Wrow + colBase + bC + 4);

        __syncthreads();
#pragma unroll
        for (int k = 0; k < BK; ++k) {
            // A: 4 packed pairs = rows (ty*8+2i, ty*8+2i+1)
            ulonglong2 aLo = *(const ulonglong2*)&As[k][ty * 8];
            ulonglong2 aHi = *(const ulonglong2*)&As[k][ty * 8 + 4];
            unsigned long long a2[4] = {aLo.x, aLo.y, aHi.x, aHi.y};
            // B: 8 scalars, splat to pairs
            uint4 bu0 = *(const uint4*)&Bs[k][tx * 8];
            uint4 bu1 = *(const uint4*)&Bs[k][tx * 8 + 4];
            unsigned long long b2[8];
            asm("mov.b64 %0, {%1,%1};" : "=l"(b2[0]) : "r"(bu0.x));
            asm("mov.b64 %0, {%1,%1};" : "=l"(b2[1]) : "r"(bu0.y));
            asm("mov.b64 %0, {%1,%1};" : "=l"(b2[2]) : "r"(bu0.z));
            asm("mov.b64 %0, {%1,%1};" : "=l"(b2[3]) : "r"(bu0.w));
            asm("mov.b64 %0, {%1,%1};" : "=l"(b2[4]) : "r"(bu1.x));
            asm("mov.b64 %0, {%1,%1};" : "=l"(b2[5]) : "r"(bu1.y));
            asm("mov.b64 %0, {%1,%1};" : "=l"(b2[6]) : "r"(bu1.z));
            asm("mov.b64 %0, {%1,%1};" : "=l"(b2[7]) : "r"(bu1.w));
#pragma unroll
            for (int i = 0; i < 4; i++)
#pragma unroll
                for (int j = 0; j < 8; j++)
                    asm("fma.rn.f32x2 %0, %1, %2, %0;"
                        : "+l"(acc2[i][j]) : "l"(a2[i]), "l"(b2[j]));
        }
        __syncthreads();
    }

    // ---- epilogue: unpack, +bias, relu, store ----
    float4 bb0 = *(const float4*)(bias + colBase + tx * 8);
    float4 bb1 = *(const float4*)(bias + colBase + tx * 8 + 4);
    float bb[8] = {bb0.x, bb0.y, bb0.z, bb0.w, bb1.x, bb1.y, bb1.z, bb1.w};

#pragma unroll
    for (int i = 0; i < 4; i++) {
        float lo[8], hi[8];
#pragma unroll
        for (int j = 0; j < 8; j++) {
            unsigned int l, h;
            asm("mov.b64 {%0,%1}, %2;" : "=r"(l), "=r"(h) : "l"(acc2[i][j]));
            lo[j] = __uint_as_float(l) + bb[j];
            hi[j] = __uint_as_float(h) + bb[j];
            if (doRelu) { lo[j] = fmaxf(lo[j], 0.f); hi[j] = fmaxf(hi[j], 0.f); }
        }
        int r0 = rowBase + ty * 8 + 2 * i;
        float* p0 = C + (size_t)r0 * DH + colBase + tx * 8;
        float* p1 = p0 + DH;
        *(float4*)(p0)     = make_float4(lo[0], lo[1], lo[2], lo[3]);
        *(float4*)(p0 + 4) = make_float4(lo[4], lo[5], lo[6], lo[7]);
        *(float4*)(p1)     = make_float4(hi[0], hi[1], hi[2], hi[3]);
        *(float4*)(p1 + 4) = make_float4(hi[4], hi[5], hi[6], hi[7]);
    }
}

// ---------------- final layer: [1024 x 47] logits + log_softmax -------------
// One block per target row. K = 256(agg, scaled by 1/cnt) + 256(self).
__global__ void __launch_bounds__(64)
final_layer(const float* __restrict__ agg, const float* __restrict__ cnt,
            const float* __restrict__ h,
            const float* __restrict__ Wl, const float* __restrict__ Wr,
            const float* __restrict__ bias, float* __restrict__ out)
{
    __shared__ float sA[DH];
    __shared__ float sH[DH];
    __shared__ float sL[DOUT];
    __shared__ float sRed[2];

    int row = blockIdx.x;
    int tid = threadIdx.x;

    float scale = 1.0f / fmaxf(cnt[row], 1.0f);
    for (int i = tid; i < DH; i += 64) {
        sA[i] = agg[(size_t)row * DH + i] * scale;
        sH[i] = h[(size_t)row * DH + i];
    }
    __syncthreads();

    if (tid < DOUT) {
        float accv = bias[tid];
#pragma unroll 8
        for (int k = 0; k < DH; ++k) accv += sA[k] * Wl[k * DOUT + tid];
#pragma unroll 8
        for (int k = 0; k < DH; ++k) accv += sH[k] * Wr[k * DOUT + tid];
        sL[tid] = accv;
    }
    __syncthreads();

    if (tid < 32) {
        float v1 = (tid < DOUT)      ? sL[tid]      : -INFINITY;
        float v2 = (tid + 32 < DOUT) ? sL[tid + 32] : -INFINITY;
        float m = fmaxf(v1, v2);
#pragma unroll
        for (int off = 16; off > 0; off >>= 1)
            m = fmaxf(m, __shfl_xor_sync(0xffffffffu, m, off));
        float s = ((tid < DOUT)      ? expf(v1 - m) : 0.f)
                + ((tid + 32 < DOUT) ? expf(v2 - m) : 0.f);
#pragma unroll
        for (int off = 16; off > 0; off >>= 1)
            s += __shfl_xor_sync(0xffffffffu, s, off);
        if (tid == 0) { sRed[0] = m; sRed[1] = logf(s); }
    }
    __syncthreads();

    if (tid < DOUT)
        out[(size_t)row * DOUT + tid] = sL[tid] - sRed[0] - sRed[1];
}

// ---------------- launch ----------------------------------------------------
extern "C" void kernel_launch(void* const* d_in, const int* in_sizes, int n_in,
                              void* d_out, int out_size) {
    const float* x   = (const float*)d_in[0];
    const float* Wl0 = (const float*)d_in[1];
    const float* Wr0 = (const float*)d_in[2];
    const float* b0  = (const float*)d_in[3];
    const float* Wl1 = (const float*)d_in[4];
    const float* Wr1 = (const float*)d_in[5];
    const float* b1  = (const float*)d_in[6];
    const float* Wl2 = (const float*)d_in[7];
    const float* Wr2 = (const float*)d_in[8];
    const float* b2  = (const float*)d_in[9];
    const int* src0  = (const int*)d_in[10];
    const int* dst0  = (const int*)d_in[11];
    const int* src1  = (const int*)d_in[12];
    const int* dst1  = (const int*)d_in[13];
    const int* src2  = (const int*)d_in[14];
    const int* dst2  = (const int*)d_in[15];
    float* out = (float*)d_out;

    float *agg0, *cnt0, *h1, *agg1, *cnt1, *h2, *agg2, *cnt2;
    cudaGetSymbolAddress((void**)&agg0, g_agg0);
    cudaGetSymbolAddress((void**)&cnt0, g_cnt0);
    cudaGetSymbolAddress((void**)&h1,   g_h1);
    cudaGetSymbolAddress((void**)&agg1, g_agg1);
    cudaGetSymbolAddress((void**)&cnt1, g_cnt1);
    cudaGetSymbolAddress((void**)&h2,   g_h2);
    cudaGetSymbolAddress((void**)&agg2, g_agg2);
    cudaGetSymbolAddress((void**)&cnt2, g_cnt2);

    // ---- layer 0 ----
    zero_agg<<<(N1c * (DIN/4) + 255) / 256, 256>>>((float4*)agg0, cnt0, N1c * (DIN/4), N1c);
    scatter_x<<<E0c / 8, 256>>>(src0, dst0, x, agg0, cnt0, E0c);
    sage_gemm2<DIN, DIN><<<dim3(N1c / 128, 2), 256>>>(agg0, cnt0, x, Wl0, Wr0, b0, h1, 1);

    // ---- layer 1 ----
    zero_agg<<<(N2c * (DH/4) + 255) / 256, 256>>>((float4*)agg1, cnt1, N2c * (DH/4), N2c);
    scatter_h<<<E1c / 8, 256>>>(src1, dst1, h1, agg1, cnt1, E1c);
    sage_gemm2<DH, DH><<<dim3(N2c / 128, 2), 256>>>(agg1, cnt1, h1, Wl1, Wr1, b1, h2, 1);

    // ---- layer 2 ----
    zero_agg<<<(N3c * (DH/4) + 255) / 256, 256>>>((float4*)agg2, cnt2, N3c * (DH/4), N3c);
    scatter_h<<<E2c / 8, 256>>>(src2, dst2, h2, agg2, cnt2, E2c);
    final_layer<<<N3c, 64>>>(agg2, cnt2, h2, Wl2, Wr2, b2, out);
}

// round 5
// speedup vs baseline: 1.3075x; 1.2896x over previous
#include <cuda_runtime.h>
#include <cuda_bf16.h>
#include <math.h>
#include <stdint.h>

// Problem constants
#define N0c  1982464
#define N1c  123904
#define N2c  11264
#define N3c  1024
#define E0c  1858560
#define E1c  112640
#define E2c  10240
#define DIN  128
#define DH   256
#define DOUT 47

// ---------------- scratch ---------------------------------------------------
__device__ float g_agg0[(size_t)N1c * DIN];
__device__ float g_cnt0[N1c];
__device__ float g_h1[(size_t)N1c * DH];
__device__ float g_agg1[(size_t)N2c * DH];
__device__ float g_cnt1[N2c];
__device__ float g_h2[(size_t)N2c * DH];
__device__ float g_agg2[(size_t)N3c * DH];
__device__ float g_cnt2[N3c];
// split bf16 transposed weights [n][k]
__device__ unsigned short g_wt0h[256 * 256];
__device__ unsigned short g_wt0l[256 * 256];
__device__ unsigned short g_wt1h[256 * 512];
__device__ unsigned short g_wt1l[256 * 512];

// ---------------- zero ------------------------------------------------------
__global__ void zero_agg(float4* agg4, float* cnt, int n4, int ncnt) {
    int i = blockIdx.x * blockDim.x + threadIdx.x;
    if (i < n4)   agg4[i] = make_float4(0.f, 0.f, 0.f, 0.f);
    if (i < ncnt) cnt[i]  = 0.f;
}

// ---------------- scatter: one warp per edge --------------------------------
__device__ __forceinline__ void red_v4(float* p, float4 v) {
    asm volatile("red.global.add.v4.f32 [%0], {%1,%2,%3,%4};"
                 :: "l"(p), "f"(v.x), "f"(v.y), "f"(v.z), "f"(v.w) : "memory");
}

__global__ void scatter_x(const int* __restrict__ src, const int* __restrict__ dst,
                          const float* __restrict__ x, float* __restrict__ agg,
                          float* __restrict__ cnt, int E) {
    int e    = (blockIdx.x * blockDim.x + threadIdx.x) >> 5;
    int lane = threadIdx.x & 31;
    if (e >= E) return;
    int s = src[e], d = dst[e];
    const float4* xr = (const float4*)(x + (size_t)s * DIN);
    float4 v = xr[lane];
    red_v4(agg + (size_t)d * DIN + lane * 4, v);
    if (lane == 0) atomicAdd(cnt + d, 1.0f);
}

__global__ void scatter_h(const int* __restrict__ src, const int* __restrict__ dst,
                          const float* __restrict__ h, float* __restrict__ agg,
                          float* __restrict__ cnt, int E) {
    int e    = (blockIdx.x * blockDim.x + threadIdx.x) >> 5;
    int lane = threadIdx.x & 31;
    if (e >= E) return;
    int s = src[e], d = dst[e];
    const float4* hr = (const float4*)(h + (size_t)s * DH);
    float4 v0 = hr[lane];
    float4 v1 = hr[lane + 32];
    red_v4(agg + (size_t)d * DH + lane * 4,        v0);
    red_v4(agg + (size_t)d * DH + (lane + 32) * 4, v1);
    if (lane == 0) atomicAdd(cnt + d, 1.0f);
}

// ---------------- weight prep: split bf16, transposed [n][k] ----------------
__global__ void build_wt_split(const float* __restrict__ Wl, const float* __restrict__ Wr,
                               unsigned short* __restrict__ WtH,
                               unsigned short* __restrict__ WtL, int KA, int K) {
    int idx = blockIdx.x * blockDim.x + threadIdx.x;
    if (idx >= 256 * K) return;
    int n = idx / K, k = idx % K;
    float w = (k < KA) ? Wl[(size_t)k * DH + n] : Wr[(size_t)(k - KA) * DH + n];
    __nv_bfloat16 hi = __float2bfloat16(w);
    __nv_bfloat16 lo = __float2bfloat16(w - __bfloat162float(hi));
    WtH[idx] = __bfloat16_as_ushort(hi);
    WtL[idx] = __bfloat16_as_ushort(lo);
}

// ---------------- mma.sync bf16 helper --------------------------------------
__device__ __forceinline__ void mma16816(float* c, uint32_t a0, uint32_t a1,
                                         uint32_t a2, uint32_t a3,
                                         uint32_t b0, uint32_t b1) {
    asm volatile(
        "mma.sync.aligned.m16n8k16.row.col.f32.bf16.bf16.f32 "
        "{%0,%1,%2,%3}, {%4,%5,%6,%7}, {%8,%9}, {%0,%1,%2,%3};"
        : "+f"(c[0]), "+f"(c[1]), "+f"(c[2]), "+f"(c[3])
        : "r"(a0), "r"(a1), "r"(a2), "r"(a3), "r"(b0), "r"(b1));
}

// ---------------- bf16-split tensor-core SAGE GEMM --------------------------
// C[M,256] = relu( [A1/cnt | A2][M,K] @ Wt^T + b ), Wt: [256,K] bf16 hi/lo
// Block: 128 threads (4 warps), tile 128M x 128N; warp tile 64x64.
// K staged in 32-wide chunks; A converted fp32->split bf16 on load.
#define SSTR 40   // smem row stride in bf16 elements (80B: conflict-free frags)
template<int KA, int KB>
__global__ void __launch_bounds__(128)
sage_gemm_mma(const float* __restrict__ A1, const float* __restrict__ cnt,
              const float* __restrict__ A2,
              const unsigned short* __restrict__ WtH,
              const unsigned short* __restrict__ WtL,
              const float* __restrict__ bias, float* __restrict__ C)
{
    __shared__ __align__(16) unsigned short sAh[128 * SSTR];
    __shared__ __align__(16) unsigned short sAl[128 * SSTR];
    __shared__ __align__(16) unsigned short sBh[128 * SSTR];
    __shared__ __align__(16) unsigned short sBl[128 * SSTR];

    const int tid  = threadIdx.x;
    const int w    = tid >> 5;
    const int lane = tid & 31;
    const int g    = lane >> 2;    // 0..7
    const int tg   = lane & 3;     // 0..3

    const int rowBase = blockIdx.x * 128;
    const int colBase = blockIdx.y * 128;
    const int mW = (w >> 1) * 64;  // warp M offset
    const int nW = (w & 1) * 64;   // warp N offset

    const int K   = KA + KB;
    const int NCH = K / 32;

    float acc[4][8][4];
#pragma unroll
    for (int i = 0; i < 4; i++)
#pragma unroll
        for (int j = 0; j < 8; j++)
#pragma unroll
            for (int q = 0; q < 4; q++) acc[i][j][q] = 0.f;

    for (int c = 0; c < NCH; ++c) {
        const int kb = c * 32;
        __syncthreads();   // previous k-step finished reading smem

        // ---- load + split A chunk: 128 rows x 32 k ----
        {
            const bool fromA1 = (kb < KA);
#pragma unroll
            for (int it = 0; it < 8; ++it) {
                int f  = it * 128 + tid;         // 0..1023 float4 slots
                int m  = f >> 3;                 // row 0..127
                int kq = f & 7;                  // float4 within chunk
                const float* srcp = fromA1
                    ? A1 + (size_t)(rowBase + m) * KA + kb
                    : A2 + (size_t)(rowBase + m) * KB + (kb - KA);
                float4 v = *(const float4*)(srcp + kq * 4);
                if (fromA1) {
                    float sc = 1.0f / fmaxf(cnt[rowBase + m], 1.0f);
                    v.x *= sc; v.y *= sc; v.z *= sc; v.w *= sc;
                }
                __nv_bfloat162 h0 = __floats2bfloat162_rn(v.x, v.y);
                __nv_bfloat162 h1 = __floats2bfloat162_rn(v.z, v.w);
                __nv_bfloat162 l0 = __floats2bfloat162_rn(
                    v.x - __bfloat162float(h0.x), v.y - __bfloat162float(h0.y));
                __nv_bfloat162 l1 = __floats2bfloat162_rn(
                    v.z - __bfloat162float(h1.x), v.w - __bfloat162float(h1.y));
                uint2 hp = make_uint2(*(uint32_t*)&h0, *(uint32_t*)&h1);
                uint2 lp = make_uint2(*(uint32_t*)&l0, *(uint32_t*)&l1);
                *(uint2*)&sAh[m * SSTR + kq * 4] = hp;
                *(uint2*)&sAl[m * SSTR + kq * 4] = lp;
            }
        }
        // ---- load B chunk: 128 n-rows x 32 k (bf16, pre-split) ----
        {
            const int n = colBase + tid;
            const uint4* ph = (const uint4*)(WtH + (size_t)n * K + kb);
            const uint4* pl = (const uint4*)(WtL + (size_t)n * K + kb);
#pragma unroll
            for (int q = 0; q < 4; ++q) {
                *(uint4*)&sBh[tid * SSTR + q * 8] = ph[q];
                *(uint4*)&sBl[tid * SSTR + q * 8] = pl[q];
            }
        }
        __syncthreads();

        // ---- two k16 steps ----
#pragma unroll
        for (int ks = 0; ks < 2; ++ks) {
            const int ko = ks * 16;
            uint32_t ah[4][4], al[4][4];
#pragma unroll
            for (int i = 0; i < 4; ++i) {
                int r0 = (mW + 16 * i + g) * SSTR + ko + 2 * tg;
                int r1 = r0 + 8 * SSTR;
                ah[i][0] = *(const uint32_t*)&sAh[r0];
                ah[i][1] = *(const uint32_t*)&sAh[r1];
                ah[i][2] = *(const uint32_t*)&sAh[r0 + 8];
                ah[i][3] = *(const uint32_t*)&sAh[r1 + 8];
                al[i][0] = *(const uint32_t*)&sAl[r0];
                al[i][1] = *(const uint32_t*)&sAl[r1];
                al[i][2] = *(const uint32_t*)&sAl[r0 + 8];
                al[i][3] = *(const uint32_t*)&sAl[r1 + 8];
            }
#pragma unroll
            for (int j = 0; j < 8; ++j) {
                int nb = (nW + 8 * j + g) * SSTR + ko + 2 * tg;
                uint32_t bh0 = *(const uint32_t*)&sBh[nb];
                uint32_t bh1 = *(const uint32_t*)&sBh[nb + 8];
                uint32_t bl0 = *(const uint32_t*)&sBl[nb];
                uint32_t bl1 = *(const uint32_t*)&sBl[nb + 8];
#pragma unroll
                for (int i = 0; i < 4; ++i) {
                    mma16816(acc[i][j], ah[i][0], ah[i][1], ah[i][2], ah[i][3], bh0, bh1);
                    mma16816(acc[i][j], ah[i][0], ah[i][1], ah[i][2], ah[i][3], bl0, bl1);
                    mma16816(acc[i][j], al[i][0], al[i][1], al[i][2], al[i][3], bh0, bh1);
                }
            }
        }
    }

    // ---- epilogue: +bias, relu, store ----
#pragma unroll
    for (int i = 0; i < 4; ++i) {
        int row0 = rowBase + mW + 16 * i + g;
        int row1 = row0 + 8;
#pragma unroll
        for (int j = 0; j < 8; ++j) {
            int col = colBase + nW + 8 * j + 2 * tg;
            float2 bb = *(const float2*)(bias + col);
            float2 o0, o1;
            o0.x = fmaxf(acc[i][j][0] + bb.x, 0.f);
            o0.y = fmaxf(acc[i][j][1] + bb.y, 0.f);
            o1.x = fmaxf(acc[i][j][2] + bb.x, 0.f);
            o1.y = fmaxf(acc[i][j][3] + bb.y, 0.f);
            *(float2*)(C + (size_t)row0 * DH + col) = o0;
            *(float2*)(C + (size_t)row1 * DH + col) = o1;
        }
    }
}

// ---------------- final layer: [1024 x 47] logits + log_softmax -------------
__global__ void __launch_bounds__(64)
final_layer(const float* __restrict__ agg, const float* __restrict__ cnt,
            const float* __restrict__ h,
            const float* __restrict__ Wl, const float* __restrict__ Wr,
            const float* __restrict__ bias, float* __restrict__ out)
{
    __shared__ float sA[DH];
    __shared__ float sH[DH];
    __shared__ float sL[DOUT];
    __shared__ float sRed[2];

    int row = blockIdx.x;
    int tid = threadIdx.x;

    float scale = 1.0f / fmaxf(cnt[row], 1.0f);
    for (int i = tid; i < DH; i += 64) {
        sA[i] = agg[(size_t)row * DH + i] * scale;
        sH[i] = h[(size_t)row * DH + i];
    }
    __syncthreads();

    if (tid < DOUT) {
        float accv = bias[tid];
#pragma unroll 8
        for (int k = 0; k < DH; ++k) accv += sA[k] * Wl[k * DOUT + tid];
#pragma unroll 8
        for (int k = 0; k < DH; ++k) accv += sH[k] * Wr[k * DOUT + tid];
        sL[tid] = accv;
    }
    __syncthreads();

    if (tid < 32) {
        float v1 = (tid < DOUT)      ? sL[tid]      : -INFINITY;
        float v2 = (tid + 32 < DOUT) ? sL[tid + 32] : -INFINITY;
        float m = fmaxf(v1, v2);
#pragma unroll
        for (int off = 16; off > 0; off >>= 1)
            m = fmaxf(m, __shfl_xor_sync(0xffffffffu, m, off));
        float s = ((tid < DOUT)      ? expf(v1 - m) : 0.f)
                + ((tid + 32 < DOUT) ? expf(v2 - m) : 0.f);
#pragma unroll
        for (int off = 16; off > 0; off >>= 1)
            s += __shfl_xor_sync(0xffffffffu, s, off);
        if (tid == 0) { sRed[0] = m; sRed[1] = logf(s); }
    }
    __syncthreads();

    if (tid < DOUT)
        out[(size_t)row * DOUT + tid] = sL[tid] - sRed[0] - sRed[1];
}

// ---------------- launch ----------------------------------------------------
extern "C" void kernel_launch(void* const* d_in, const int* in_sizes, int n_in,
                              void* d_out, int out_size) {
    const float* x   = (const float*)d_in[0];
    const float* Wl0 = (const float*)d_in[1];
    const float* Wr0 = (const float*)d_in[2];
    const float* b0  = (const float*)d_in[3];
    const float* Wl1 = (const float*)d_in[4];
    const float* Wr1 = (const float*)d_in[5];
    const float* b1  = (const float*)d_in[6];
    const float* Wl2 = (const float*)d_in[7];
    const float* Wr2 = (const float*)d_in[8];
    const float* b2  = (const float*)d_in[9];
    const int* src0  = (const int*)d_in[10];
    const int* dst0  = (const int*)d_in[11];
    const int* src1  = (const int*)d_in[12];
    const int* dst1  = (const int*)d_in[13];
    const int* src2  = (const int*)d_in[14];
    const int* dst2  = (const int*)d_in[15];
    float* out = (float*)d_out;

    float *agg0, *cnt0, *h1, *agg1, *cnt1, *h2, *agg2, *cnt2;
    unsigned short *wt0h, *wt0l, *wt1h, *wt1l;
    cudaGetSymbolAddress((void**)&agg0, g_agg0);
    cudaGetSymbolAddress((void**)&cnt0, g_cnt0);
    cudaGetSymbolAddress((void**)&h1,   g_h1);
    cudaGetSymbolAddress((void**)&agg1, g_agg1);
    cudaGetSymbolAddress((void**)&cnt1, g_cnt1);
    cudaGetSymbolAddress((void**)&h2,   g_h2);
    cudaGetSymbolAddress((void**)&agg2, g_agg2);
    cudaGetSymbolAddress((void**)&cnt2, g_cnt2);
    cudaGetSymbolAddress((void**)&wt0h, g_wt0h);
    cudaGetSymbolAddress((void**)&wt0l, g_wt0l);
    cudaGetSymbolAddress((void**)&wt1h, g_wt1h);
    cudaGetSymbolAddress((void**)&wt1l, g_wt1l);

    // ---- layer 0 ----
    build_wt_split<<<(256 * 256 + 255) / 256, 256>>>(Wl0, Wr0, wt0h, wt0l, DIN, 256);
    zero_agg<<<(N1c * (DIN/4) + 255) / 256, 256>>>((float4*)agg0, cnt0, N1c * (DIN/4), N1c);
    scatter_x<<<E0c / 8, 256>>>(src0, dst0, x, agg0, cnt0, E0c);
    sage_gemm_mma<DIN, DIN><<<dim3(N1c / 128, 2), 128>>>(agg0, cnt0, x, wt0h, wt0l, b0, h1);

    // ---- layer 1 ----
    build_wt_split<<<(256 * 512 + 255) / 256, 256>>>(Wl1, Wr1, wt1h, wt1l, DH, 512);
    zero_agg<<<(N2c * (DH/4) + 255) / 256, 256>>>((float4*)agg1, cnt1, N2c * (DH/4), N2c);
    scatter_h<<<E1c / 8, 256>>>(src1, dst1, h1, agg1, cnt1, E1c);
    sage_gemm_mma<DH, DH><<<dim3(N2c / 128, 2), 128>>>(agg1, cnt1, h1, wt1h, wt1l, b1, h2);

    // ---- layer 2 ----
    zero_agg<<<(N3c * (DH/4) + 255) / 256, 256>>>((float4*)agg2, cnt2, N3c * (DH/4), N3c);
    scatter_h<<<E2c / 8, 256>>>(src2, dst2, h2, agg2, cnt2, E2c);
    final_layer<<<N3c, 64>>>(agg2, cnt2, h2, Wl2, Wr2, b2, out);
}

// round 8
// speedup vs baseline: 1.4401x; 1.1014x over previous
#include <cuda_runtime.h>
#include <cuda_bf16.h>
#include <math.h>
#include <stdint.h>

#define N0c  1982464
#define N1c  123904
#define N2c  11264
#define N3c  1024
#define E0c  1858560
#define E1c  112640
#define E2c  10240
#define DIN  128
#define DH   256
#define DOUT 47

typedef unsigned short ushort_t;

// ---------------- scratch ---------------------------------------------------
__device__ float g_agg0[(size_t)N1c * DIN];
__device__ float g_cnt0[N1c];
__device__ float g_h1[(size_t)N1c * DH];
__device__ float g_agg1[(size_t)N2c * DH];
__device__ float g_cnt1[N2c];
__device__ float g_h2[(size_t)N2c * DH];
__device__ float g_agg2[(size_t)N3c * DH];
__device__ float g_cnt2[N3c];
// split bf16 transposed weights [n][k]
__device__ ushort_t g_wt0h[256 * 256];
__device__ ushort_t g_wt0l[256 * 256];
__device__ ushort_t g_wt1h[256 * 512];
__device__ ushort_t g_wt1l[256 * 512];
// split bf16 A matrices [m][k] (concat [agg/cnt | self])
__device__ ushort_t g_Ah0[(size_t)N1c * 256];
__device__ ushort_t g_Al0[(size_t)N1c * 256];
__device__ ushort_t g_Ah1[(size_t)N2c * 512];
__device__ ushort_t g_Al1[(size_t)N2c * 512];

// ---------------- zero ------------------------------------------------------
__global__ void zero_agg(float4* agg4, float* cnt, int n4, int ncnt) {
    int i = blockIdx.x * blockDim.x + threadIdx.x;
    if (i < n4)   agg4[i] = make_float4(0.f, 0.f, 0.f, 0.f);
    if (i < ncnt) cnt[i]  = 0.f;
}

// ---------------- scatter: one warp per edge --------------------------------
__device__ __forceinline__ void red_v4(float* p, float4 v) {
    asm volatile("red.global.add.v4.f32 [%0], {%1,%2,%3,%4};"
                 :: "l"(p), "f"(v.x), "f"(v.y), "f"(v.z), "f"(v.w) : "memory");
}

__global__ void scatter_x(const int* __restrict__ src, const int* __restrict__ dst,
                          const float* __restrict__ x, float* __restrict__ agg,
                          float* __restrict__ cnt, int E) {
    int e    = (blockIdx.x * blockDim.x + threadIdx.x) >> 5;
    int lane = threadIdx.x & 31;
    if (e >= E) return;
    int s = src[e], d = dst[e];
    const float4* xr = (const float4*)(x + (size_t)s * DIN);
    float4 v = xr[lane];
    red_v4(agg + (size_t)d * DIN + lane * 4, v);
    if (lane == 0) atomicAdd(cnt + d, 1.0f);
}

__global__ void scatter_h(const int* __restrict__ src, const int* __restrict__ dst,
                          const float* __restrict__ h, float* __restrict__ agg,
                          float* __restrict__ cnt, int E) {
    int e    = (blockIdx.x * blockDim.x + threadIdx.x) >> 5;
    int lane = threadIdx.x & 31;
    if (e >= E) return;
    int s = src[e], d = dst[e];
    const float4* hr = (const float4*)(h + (size_t)s * DH);
    float4 v0 = hr[lane];
    float4 v1 = hr[lane + 32];
    red_v4(agg + (size_t)d * DH + lane * 4,        v0);
    red_v4(agg + (size_t)d * DH + (lane + 32) * 4, v1);
    if (lane == 0) atomicAdd(cnt + d, 1.0f);
}

// ---------------- weight prep: split bf16, transposed [n][k] ----------------
__global__ void build_wt_split(const float* __restrict__ Wl, const float* __restrict__ Wr,
                               ushort_t* __restrict__ WtH,
                               ushort_t* __restrict__ WtL, int KA, int K) {
    int idx = blockIdx.x * blockDim.x + threadIdx.x;
    if (idx >= 256 * K) return;
    int n = idx / K, k = idx % K;
    float w = (k < KA) ? Wl[(size_t)k * DH + n] : Wr[(size_t)(k - KA) * DH + n];
    __nv_bfloat16 hi = __float2bfloat16(w);
    __nv_bfloat16 lo = __float2bfloat16(w - __bfloat162float(hi));
    WtH[idx] = __bfloat16_as_ushort(hi);
    WtL[idx] = __bfloat16_as_ushort(lo);
}

// ---------------- A prep: normalize + split to bf16 hi/lo -------------------
// A = [agg/max(cnt,1) | self], out [m][KA+KB] bf16. One thread = 8 k-elems.
__global__ void split_A(const float* __restrict__ agg, const float* __restrict__ cnt,
                        const float* __restrict__ self,
                        ushort_t* __restrict__ Ah, ushort_t* __restrict__ Al,
                        int KA, int KB, int M)
{
    const int K = KA + KB;
    const int perRow = K / 8;
    int idx = blockIdx.x * blockDim.x + threadIdx.x;
    if (idx >= M * perRow) return;
    int row = idx / perRow;
    int k   = (idx % perRow) * 8;

    const float* srcp;
    float sc;
    if (k < KA) { srcp = agg + (size_t)row * KA + k; sc = 1.0f / fmaxf(cnt[row], 1.0f); }
    else        { srcp = self + (size_t)row * KB + (k - KA); sc = 1.0f; }

    float4 v0 = *(const float4*)(srcp);
    float4 v1 = *(const float4*)(srcp + 4);
    float f[8] = {v0.x*sc, v0.y*sc, v0.z*sc, v0.w*sc, v1.x*sc, v1.y*sc, v1.z*sc, v1.w*sc};
    ushort_t hs[8], ls[8];
#pragma unroll
    for (int i = 0; i < 8; ++i) {
        __nv_bfloat16 hb = __float2bfloat16(f[i]);
        __nv_bfloat16 lb = __float2bfloat16(f[i] - __bfloat162float(hb));
        hs[i] = __bfloat16_as_ushort(hb);
        ls[i] = __bfloat16_as_ushort(lb);
    }
    *(uint4*)(Ah + (size_t)row * K + k) = *(uint4*)hs;
    *(uint4*)(Al + (size_t)row * K + k) = *(uint4*)ls;
}

// ---------------- mma.sync bf16 helper --------------------------------------
__device__ __forceinline__ void mma16816(float* c, uint32_t a0, uint32_t a1,
                                         uint32_t a2, uint32_t a3,
                                         uint32_t b0, uint32_t b1) {
    asm volatile(
        "mma.sync.aligned.m16n8k16.row.col.f32.bf16.bf16.f32 "
        "{%0,%1,%2,%3}, {%4,%5,%6,%7}, {%8,%9}, {%0,%1,%2,%3};"
        : "+f"(c[0]), "+f"(c[1]), "+f"(c[2]), "+f"(c[3])
        : "r"(a0), "r"(a1), "r"(a2), "r"(a3), "r"(b0), "r"(b1));
}
__device__ __forceinline__ void cpa16(uint32_t dst, const void* src) {
    asm volatile("cp.async.ca.shared.global [%0], [%1], 16;" :: "r"(dst), "l"(src));
}

// ---------------- pipelined bf16-split tensor-core GEMM ---------------------
// C[M, 256] tile: CTA = 128(M) x BN(N), 256 threads (8 warps), warp 64 x BN/4.
// A: [m][K] bf16 hi/lo. B (Wt): [n][K] bf16 hi/lo. 3-pass error compensation.
#define SSTR 40   // smem row stride in ushorts (80B)
template<int K, int BN>
__global__ void __launch_bounds__(256)
gemm3p(const ushort_t* __restrict__ Ah, const ushort_t* __restrict__ Al,
       const ushort_t* __restrict__ WtH, const ushort_t* __restrict__ WtL,
       const float* __restrict__ bias, float* __restrict__ C)
{
    extern __shared__ ushort_t sm[];
    constexpr int ASZ = 128 * SSTR;        // per A array (ushorts)
    constexpr int BSZ = BN * SSTR;         // per B array
    constexpr int STG = 2 * ASZ + 2 * BSZ; // stage stride (ushorts)
    constexpr int WN  = BN / 4;            // warp N width (64 or 32)
    constexpr int NJ  = WN / 8;            // 8 or 4
    constexpr int NCH = K / 32;
    constexpr int BCH = BN * 4 / 256;      // B cp.async chunks per thread per array

    const int tid  = threadIdx.x;
    const int w    = tid >> 5;
    const int lane = tid & 31;
    const int g    = lane >> 2;
    const int tg   = lane & 3;

    const int rowBase = blockIdx.x * 128;
    const int colBase = blockIdx.y * BN;
    const int mW = (w >> 2) * 64;
    const int nW = (w & 3) * WN;

    const uint32_t smB = (uint32_t)__cvta_generic_to_shared(sm);

    float acc[4][NJ][4];
#pragma unroll
    for (int i = 0; i < 4; i++)
#pragma unroll
        for (int j = 0; j < NJ; j++)
#pragma unroll
            for (int q = 0; q < 4; q++) acc[i][j][q] = 0.f;

    // ---- stage loader (cp.async) ----
    auto load_stage = [&](int c, int buf) {
        const int kb = c * 32;
        const uint32_t sb = smB + (uint32_t)buf * STG * 2;
#pragma unroll
        for (int t = 0; t < 2; ++t) {                // A: 512 chunks / 256 thr
            int chunk = tid + t * 256;
            int row = chunk >> 2, c4 = chunk & 3;
            uint32_t d = sb + (uint32_t)(row * SSTR + c4 * 8) * 2;
            const size_t go = (size_t)(rowBase + row) * K + kb + c4 * 8;
            cpa16(d,           Ah + go);
            cpa16(d + ASZ * 2, Al + go);
        }
#pragma unroll
        for (int t = 0; t < BCH; ++t) {              // B: BN*4 chunks / 256 thr
            int chunk = tid + t * 256;
            int row = chunk >> 2, c4 = chunk & 3;
            uint32_t d = sb + (uint32_t)(2 * ASZ + row * SSTR + c4 * 8) * 2;
            const size_t go = (size_t)(colBase + row) * K + kb + c4 * 8;
            cpa16(d,           WtH + go);
            cpa16(d + BSZ * 2, WtL + go);
        }
        asm volatile("cp.async.commit_group;" ::: "memory");
    };

    load_stage(0, 0);
    for (int c = 0; c < NCH; ++c) {
        if (c + 1 < NCH) {
            load_stage(c + 1, (c + 1) & 1);
            asm volatile("cp.async.wait_group 1;" ::: "memory");
        } else {
            asm volatile("cp.async.wait_group 0;" ::: "memory");
        }
        __syncthreads();

        const ushort_t* sAh = sm + (c & 1) * STG;
        const ushort_t* sAl = sAh + ASZ;
        const ushort_t* sBh = sAh + 2 * ASZ;
        const ushort_t* sBl = sBh + BSZ;

#pragma unroll
        for (int ks = 0; ks < 2; ++ks) {
            const int ko = ks * 16;
            uint32_t ah[4][4], al[4][4];
#pragma unroll
            for (int i = 0; i < 4; ++i) {
                int r0 = (mW + 16 * i + g) * SSTR + ko + 2 * tg;
                int r1 = r0 + 8 * SSTR;
                ah[i][0] = *(const uint32_t*)&sAh[r0];
                ah[i][1] = *(const uint32_t*)&sAh[r1];
                ah[i][2] = *(const uint32_t*)&sAh[r0 + 8];
                ah[i][3] = *(const uint32_t*)&sAh[r1 + 8];
                al[i][0] = *(const uint32_t*)&sAl[r0];
                al[i][1] = *(const uint32_t*)&sAl[r1];
                al[i][2] = *(const uint32_t*)&sAl[r0 + 8];
                al[i][3] = *(const uint32_t*)&sAl[r1 + 8];
            }
#pragma unroll
            for (int j = 0; j < NJ; ++j) {
                int nb = (nW + 8 * j + g) * SSTR + ko + 2 * tg;
                uint32_t bh0 = *(const uint32_t*)&sBh[nb];
                uint32_t bh1 = *(const uint32_t*)&sBh[nb + 8];
                uint32_t bl0 = *(const uint32_t*)&sBl[nb];
                uint32_t bl1 = *(const uint32_t*)&sBl[nb + 8];
#pragma unroll
                for (int i = 0; i < 4; ++i) {
                    mma16816(acc[i][j], ah[i][0], ah[i][1], ah[i][2], ah[i][3], bh0, bh1);
                    mma16816(acc[i][j], ah[i][0], ah[i][1], ah[i][2], ah[i][3], bl0, bl1);
                    mma16816(acc[i][j], al[i][0], al[i][1], al[i][2], al[i][3], bh0, bh1);
                }
            }
        }
        __syncthreads();
    }

    // ---- epilogue: +bias, relu, store ----
#pragma unroll
    for (int i = 0; i < 4; ++i) {
        int row0 = rowBase + mW + 16 * i + g;
        int row1 = row0 + 8;
#pragma unroll
        for (int j = 0; j < NJ; ++j) {
            int col = colBase + nW + 8 * j + 2 * tg;
            float2 bb = *(const float2*)(bias + col);
            float2 o0, o1;
            o0.x = fmaxf(acc[i][j][0] + bb.x, 0.f);
            o0.y = fmaxf(acc[i][j][1] + bb.y, 0.f);
            o1.x = fmaxf(acc[i][j][2] + bb.x, 0.f);
            o1.y = fmaxf(acc[i][j][3] + bb.y, 0.f);
            *(float2*)(C + (size_t)row0 * DH + col) = o0;
            *(float2*)(C + (size_t)row1 * DH + col) = o1;
        }
    }
}

// ---------------- final layer: [1024 x 47] logits + log_softmax -------------
__global__ void __launch_bounds__(64)
final_layer(const float* __restrict__ agg, const float* __restrict__ cnt,
            const float* __restrict__ h,
            const float* __restrict__ Wl, const float* __restrict__ Wr,
            const float* __restrict__ bias, float* __restrict__ out)
{
    __shared__ float sA[DH];
    __shared__ float sH[DH];
    __shared__ float sL[DOUT];
    __shared__ float sRed[2];

    int row = blockIdx.x;
    int tid = threadIdx.x;

    float scale = 1.0f / fmaxf(cnt[row], 1.0f);
    for (int i = tid; i < DH; i += 64) {
        sA[i] = agg[(size_t)row * DH + i] * scale;
        sH[i] = h[(size_t)row * DH + i];
    }
    __syncthreads();

    if (tid < DOUT) {
        float accv = bias[tid];
#pragma unroll 8
        for (int k = 0; k < DH; ++k) accv += sA[k] * Wl[k * DOUT + tid];
#pragma unroll 8
        for (int k = 0; k < DH; ++k) accv += sH[k] * Wr[k * DOUT + tid];
        sL[tid] = accv;
    }
    __syncthreads();

    if (tid < 32) {
        float v1 = (tid < DOUT)      ? sL[tid]      : -INFINITY;
        float v2 = (tid + 32 < DOUT) ? sL[tid + 32] : -INFINITY;
        float m = fmaxf(v1, v2);
#pragma unroll
        for (int off = 16; off > 0; off >>= 1)
            m = fmaxf(m, __shfl_xor_sync(0xffffffffu, m, off));
        float s = ((tid < DOUT)      ? expf(v1 - m) : 0.f)
                + ((tid + 32 < DOUT) ? expf(v2 - m) : 0.f);
#pragma unroll
        for (int off = 16; off > 0; off >>= 1)
            s += __shfl_xor_sync(0xffffffffu, s, off);
        if (tid == 0) { sRed[0] = m; sRed[1] = logf(s); }
    }
    __syncthreads();

    if (tid < DOUT)
        out[(size_t)row * DOUT + tid] = sL[tid] - sRed[0] - sRed[1];
}

// ---------------- launch ----------------------------------------------------
extern "C" void kernel_launch(void* const* d_in, const int* in_sizes, int n_in,
                              void* d_out, int out_size) {
    const float* x   = (const float*)d_in[0];
    const float* Wl0 = (const float*)d_in[1];
    const float* Wr0 = (const float*)d_in[2];
    const float* b0  = (const float*)d_in[3];
    const float* Wl1 = (const float*)d_in[4];
    const float* Wr1 = (const float*)d_in[5];
    const float* b1  = (const float*)d_in[6];
    const float* Wl2 = (const float*)d_in[7];
    const float* Wr2 = (const float*)d_in[8];
    const float* b2  = (const float*)d_in[9];
    const int* src0  = (const int*)d_in[10];
    const int* dst0  = (const int*)d_in[11];
    const int* src1  = (const int*)d_in[12];
    const int* dst1  = (const int*)d_in[13];
    const int* src2  = (const int*)d_in[14];
    const int* dst2  = (const int*)d_in[15];
    float* out = (float*)d_out;

    float *agg0, *cnt0, *h1, *agg1, *cnt1, *h2, *agg2, *cnt2;
    ushort_t *wt0h, *wt0l, *wt1h, *wt1l, *Ah0, *Al0, *Ah1, *Al1;
    cudaGetSymbolAddress((void**)&agg0, g_agg0);
    cudaGetSymbolAddress((void**)&cnt0, g_cnt0);
    cudaGetSymbolAddress((void**)&h1,   g_h1);
    cudaGetSymbolAddress((void**)&agg1, g_agg1);
    cudaGetSymbolAddress((void**)&cnt1, g_cnt1);
    cudaGetSymbolAddress((void**)&h2,   g_h2);
    cudaGetSymbolAddress((void**)&agg2, g_agg2);
    cudaGetSymbolAddress((void**)&cnt2, g_cnt2);
    cudaGetSymbolAddress((void**)&wt0h, g_wt0h);
    cudaGetSymbolAddress((void**)&wt0l, g_wt0l);
    cudaGetSymbolAddress((void**)&wt1h, g_wt1h);
    cudaGetSymbolAddress((void**)&wt1l, g_wt1l);
    cudaGetSymbolAddress((void**)&Ah0,  g_Ah0);
    cudaGetSymbolAddress((void**)&Al0,  g_Al0);
    cudaGetSymbolAddress((void**)&Ah1,  g_Ah1);
    cudaGetSymbolAddress((void**)&Al1,  g_Al1);

    const int SMEM0 = (2 * 128 * SSTR + 2 * 256 * SSTR) * 2 * 2;  // K=256,BN=256: 122880B
    const int SMEM1 = (2 * 128 * SSTR + 2 * 128 * SSTR) * 2 * 2;  // K=512,BN=128: 81920B
    cudaFuncSetAttribute(gemm3p<256, 256>, cudaFuncAttributeMaxDynamicSharedMemorySize, SMEM0);
    cudaFuncSetAttribute(gemm3p<512, 128>, cudaFuncAttributeMaxDynamicSharedMemorySize, SMEM1);

    // ---- layer 0 ----
    build_wt_split<<<(256 * 256 + 255) / 256, 256>>>(Wl0, Wr0, wt0h, wt0l, DIN, 256);
    zero_agg<<<(N1c * (DIN/4) + 255) / 256, 256>>>((float4*)agg0, cnt0, N1c * (DIN/4), N1c);
    scatter_x<<<E0c / 8, 256>>>(src0, dst0, x, agg0, cnt0, E0c);
    split_A<<<(N1c * 32 + 255) / 256, 256>>>(agg0, cnt0, x, Ah0, Al0, DIN, DIN, N1c);
    gemm3p<256, 256><<<dim3(N1c / 128, 1), 256, SMEM0>>>(Ah0, Al0, wt0h, wt0l, b0, h1);

    // ---- layer 1 ----
    build_wt_split<<<(256 * 512 + 255) / 256, 256>>>(Wl1, Wr1, wt1h, wt1l, DH, 512);
    zero_agg<<<(N2c * (DH/4) + 255) / 256, 256>>>((float4*)agg1, cnt1, N2c * (DH/4), N2c);
    scatter_h<<<E1c / 8, 256>>>(src1, dst1, h1, agg1, cnt1, E1c);
    split_A<<<(N2c * 64 + 255) / 256, 256>>>(agg1, cnt1, h1, Ah1, Al1, DH, DH, N2c);
    gemm3p<512, 128><<<dim3(N2c / 128, 2), 256, SMEM1>>>(Ah1, Al1, wt1h, wt1l, b1, h2);

    // ---- layer 2 ----
    zero_agg<<<(N3c * (DH/4) + 255) / 256, 256>>>((float4*)agg2, cnt2, N3c * (DH/4), N3c);
    scatter_h<<<E2c / 8, 256>>>(src2, dst2, h2, agg2, cnt2, E2c);
    final_layer<<<N3c, 64>>>(agg2, cnt2, h2, Wl2, Wr2, b2, out);
}

// round 9
// speedup vs baseline: 1.5636x; 1.0858x over previous
#include <cuda_runtime.h>
#include <cuda_bf16.h>
#include <math.h>
#include <stdint.h>

#define N0c  1982464
#define N1c  123904
#define N2c  11264
#define N3c  1024
#define E0c  1858560
#define E1c  112640
#define E2c  10240
#define DIN  128
#define DH   256
#define DOUT 47

typedef unsigned short ushort_t;

// ---------------- scratch ---------------------------------------------------
__device__ float g_agg0[(size_t)N1c * DIN];
__device__ float g_cnt0[N1c];
__device__ float g_h1[(size_t)N1c * DH];
__device__ float g_agg1[(size_t)N2c * DH];
__device__ float g_cnt1[N2c];
__device__ float g_h2[(size_t)N2c * DH];
__device__ float g_agg2[(size_t)N3c * DH];
__device__ float g_cnt2[N3c];
__device__ ushort_t g_wt0h[256 * 256];
__device__ ushort_t g_wt0l[256 * 256];
__device__ ushort_t g_wt1h[256 * 512];
__device__ ushort_t g_wt1l[256 * 512];
__device__ ushort_t g_Ah0[(size_t)N1c * 256];
__device__ ushort_t g_Al0[(size_t)N1c * 256];
__device__ ushort_t g_Ah1[(size_t)N2c * 512];
__device__ ushort_t g_Al1[(size_t)N2c * 512];

// ---------------- zero ------------------------------------------------------
__global__ void zero_agg(float4* agg4, float* cnt, int n4, int ncnt) {
    int i = blockIdx.x * blockDim.x + threadIdx.x;
    if (i < n4)   agg4[i] = make_float4(0.f, 0.f, 0.f, 0.f);
    if (i < ncnt) cnt[i]  = 0.f;
}

// ---------------- scatter: 4 edges per warp, front-batched loads ------------
__device__ __forceinline__ void red_v4(float* p, float4 v) {
    asm volatile("red.global.add.v4.f32 [%0], {%1,%2,%3,%4};"
                 :: "l"(p), "f"(v.x), "f"(v.y), "f"(v.z), "f"(v.w) : "memory");
}

// D=128: 1 float4 per lane per edge; 4 edges batched
__global__ void scatter_x4(const int* __restrict__ src, const int* __restrict__ dst,
                           const float* __restrict__ x, float* __restrict__ agg,
                           float* __restrict__ cnt, int E) {
    int w    = (blockIdx.x * blockDim.x + threadIdx.x) >> 5;
    int lane = threadIdx.x & 31;
    int e0 = w * 4;
    if (e0 >= E) return;
    int4 s4 = *(const int4*)(src + e0);
    int4 d4 = *(const int4*)(dst + e0);
    float4 v0 = ((const float4*)(x + (size_t)s4.x * DIN))[lane];
    float4 v1 = ((const float4*)(x + (size_t)s4.y * DIN))[lane];
    float4 v2 = ((const float4*)(x + (size_t)s4.z * DIN))[lane];
    float4 v3 = ((const float4*)(x + (size_t)s4.w * DIN))[lane];
    red_v4(agg + (size_t)d4.x * DIN + lane * 4, v0);
    red_v4(agg + (size_t)d4.y * DIN + lane * 4, v1);
    red_v4(agg + (size_t)d4.z * DIN + lane * 4, v2);
    red_v4(agg + (size_t)d4.w * DIN + lane * 4, v3);
    if (lane < 4) {
        int d = (lane == 0) ? d4.x : (lane == 1) ? d4.y : (lane == 2) ? d4.z : d4.w;
        atomicAdd(cnt + d, 1.0f);
    }
}

// D=256: 2 float4 per lane per edge; 4 edges batched
__global__ void scatter_h4(const int* __restrict__ src, const int* __restrict__ dst,
                           const float* __restrict__ h, float* __restrict__ agg,
                           float* __restrict__ cnt, int E) {
    int w    = (blockIdx.x * blockDim.x + threadIdx.x) >> 5;
    int lane = threadIdx.x & 31;
    int e0 = w * 4;
    if (e0 >= E) return;
    int4 s4 = *(const int4*)(src + e0);
    int4 d4 = *(const int4*)(dst + e0);
    const float4* r0 = (const float4*)(h + (size_t)s4.x * DH);
    const float4* r1 = (const float4*)(h + (size_t)s4.y * DH);
    const float4* r2 = (const float4*)(h + (size_t)s4.z * DH);
    const float4* r3 = (const float4*)(h + (size_t)s4.w * DH);
    float4 a0 = r0[lane], b0 = r0[lane + 32];
    float4 a1 = r1[lane], b1 = r1[lane + 32];
    float4 a2 = r2[lane], b2 = r2[lane + 32];
    float4 a3 = r3[lane], b3 = r3[lane + 32];
    red_v4(agg + (size_t)d4.x * DH + lane * 4, a0);
    red_v4(agg + (size_t)d4.x * DH + (lane + 32) * 4, b0);
    red_v4(agg + (size_t)d4.y * DH + lane * 4, a1);
    red_v4(agg + (size_t)d4.y * DH + (lane + 32) * 4, b1);
    red_v4(agg + (size_t)d4.z * DH + lane * 4, a2);
    red_v4(agg + (size_t)d4.z * DH + (lane + 32) * 4, b2);
    red_v4(agg + (size_t)d4.w * DH + lane * 4, a3);
    red_v4(agg + (size_t)d4.w * DH + (lane + 32) * 4, b3);
    if (lane < 4) {
        int d = (lane == 0) ? d4.x : (lane == 1) ? d4.y : (lane == 2) ? d4.z : d4.w;
        atomicAdd(cnt + d, 1.0f);
    }
}

// ---------------- weight prep: split bf16, transposed [n][k] ----------------
__global__ void build_wt_split(const float* __restrict__ Wl, const float* __restrict__ Wr,
                               ushort_t* __restrict__ WtH,
                               ushort_t* __restrict__ WtL, int KA, int K) {
    int idx = blockIdx.x * blockDim.x + threadIdx.x;
    if (idx >= 256 * K) return;
    int n = idx / K, k = idx % K;
    float w = (k < KA) ? Wl[(size_t)k * DH + n] : Wr[(size_t)(k - KA) * DH + n];
    __nv_bfloat16 hi = __float2bfloat16(w);
    __nv_bfloat16 lo = __float2bfloat16(w - __bfloat162float(hi));
    WtH[idx] = __bfloat16_as_ushort(hi);
    WtL[idx] = __bfloat16_as_ushort(lo);
}

// ---------------- A prep: normalize + split to bf16 hi/lo -------------------
__global__ void split_A(const float* __restrict__ agg, const float* __restrict__ cnt,
                        const float* __restrict__ self,
                        ushort_t* __restrict__ Ah, ushort_t* __restrict__ Al,
                        int KA, int KB, int M)
{
    const int K = KA + KB;
    const int perRow = K / 8;
    int idx = blockIdx.x * blockDim.x + threadIdx.x;
    if (idx >= M * perRow) return;
    int row = idx / perRow;
    int k   = (idx % perRow) * 8;

    const float* srcp;
    float sc;
    if (k < KA) { srcp = agg + (size_t)row * KA + k; sc = 1.0f / fmaxf(cnt[row], 1.0f); }
    else        { srcp = self + (size_t)row * KB + (k - KA); sc = 1.0f; }

    float4 v0 = *(const float4*)(srcp);
    float4 v1 = *(const float4*)(srcp + 4);
    float f[8] = {v0.x*sc, v0.y*sc, v0.z*sc, v0.w*sc, v1.x*sc, v1.y*sc, v1.z*sc, v1.w*sc};
    ushort_t hs[8], ls[8];
#pragma unroll
    for (int i = 0; i < 8; ++i) {
        __nv_bfloat16 hb = __float2bfloat16(f[i]);
        __nv_bfloat16 lb = __float2bfloat16(f[i] - __bfloat162float(hb));
        hs[i] = __bfloat16_as_ushort(hb);
        ls[i] = __bfloat16_as_ushort(lb);
    }
    *(uint4*)(Ah + (size_t)row * K + k) = *(uint4*)hs;
    *(uint4*)(Al + (size_t)row * K + k) = *(uint4*)ls;
}

// ---------------- mma.sync bf16 helper --------------------------------------
__device__ __forceinline__ void mma16816(float* c, uint32_t a0, uint32_t a1,
                                         uint32_t a2, uint32_t a3,
                                         uint32_t b0, uint32_t b1) {
    asm volatile(
        "mma.sync.aligned.m16n8k16.row.col.f32.bf16.bf16.f32 "
        "{%0,%1,%2,%3}, {%4,%5,%6,%7}, {%8,%9}, {%0,%1,%2,%3};"
        : "+f"(c[0]), "+f"(c[1]), "+f"(c[2]), "+f"(c[3])
        : "r"(a0), "r"(a1), "r"(a2), "r"(a3), "r"(b0), "r"(b1));
}
__device__ __forceinline__ void cpa16(uint32_t dst, const void* src) {
    asm volatile("cp.async.ca.shared.global [%0], [%1], 16;" :: "r"(dst), "l"(src));
}

// ---------------- 3-stage pipelined bf16-split tensor-core GEMM -------------
#define SSTR 40
template<int K, int BN>
__global__ void __launch_bounds__(256)
gemm3p(const ushort_t* __restrict__ Ah, const ushort_t* __restrict__ Al,
       const ushort_t* __restrict__ WtH, const ushort_t* __restrict__ WtL,
       const float* __restrict__ bias, float* __restrict__ C)
{
    extern __shared__ ushort_t sm[];
    constexpr int ASZ = 128 * SSTR;
    constexpr int BSZ = BN * SSTR;
    constexpr int STG = 2 * ASZ + 2 * BSZ;
    constexpr int WN  = BN / 4;
    constexpr int NJ  = WN / 8;
    constexpr int NCH = K / 32;
    constexpr int BCH = BN * 4 / 256;

    const int tid  = threadIdx.x;
    const int w    = tid >> 5;
    const int lane = tid & 31;
    const int g    = lane >> 2;
    const int tg   = lane & 3;

    const int rowBase = blockIdx.x * 128;
    const int colBase = blockIdx.y * BN;
    const int mW = (w >> 2) * 64;
    const int nW = (w & 3) * WN;

    const uint32_t smB = (uint32_t)__cvta_generic_to_shared(sm);

    float acc[4][NJ][4];
#pragma unroll
    for (int i = 0; i < 4; i++)
#pragma unroll
        for (int j = 0; j < NJ; j++)
#pragma unroll
            for (int q = 0; q < 4; q++) acc[i][j][q] = 0.f;

    auto load_stage = [&](int c, int buf) {
        const int kb = c * 32;
        const uint32_t sb = smB + (uint32_t)buf * STG * 2;
#pragma unroll
        for (int t = 0; t < 2; ++t) {
            int chunk = tid + t * 256;
            int row = chunk >> 2, c4 = chunk & 3;
            uint32_t d = sb + (uint32_t)(row * SSTR + c4 * 8) * 2;
            const size_t go = (size_t)(rowBase + row) * K + kb + c4 * 8;
            cpa16(d,           Ah + go);
            cpa16(d + ASZ * 2, Al + go);
        }
#pragma unroll
        for (int t = 0; t < BCH; ++t) {
            int chunk = tid + t * 256;
            int row = chunk >> 2, c4 = chunk & 3;
            uint32_t d = sb + (uint32_t)(2 * ASZ + row * SSTR + c4 * 8) * 2;
            const size_t go = (size_t)(colBase + row) * K + kb + c4 * 8;
            cpa16(d,           WtH + go);
            cpa16(d + BSZ * 2, WtL + go);
        }
        asm volatile("cp.async.commit_group;" ::: "memory");
    };

    load_stage(0, 0);
    if (NCH > 1) load_stage(1, 1);

    for (int c = 0; c < NCH; ++c) {
        if (c + 1 < NCH) asm volatile("cp.async.wait_group 1;" ::: "memory");
        else             asm volatile("cp.async.wait_group 0;" ::: "memory");
        __syncthreads();
        if (c + 2 < NCH) load_stage(c + 2, (c + 2) % 3);

        const ushort_t* sAh = sm + (c % 3) * STG;
        const ushort_t* sAl = sAh + ASZ;
        const ushort_t* sBh = sAh + 2 * ASZ;
        const ushort_t* sBl = sBh + BSZ;

#pragma unroll
        for (int ks = 0; ks < 2; ++ks) {
            const int ko = ks * 16;
            uint32_t ah[4][4], al[4][4];
#pragma unroll
            for (int i = 0; i < 4; ++i) {
                int r0 = (mW + 16 * i + g) * SSTR + ko + 2 * tg;
                int r1 = r0 + 8 * SSTR;
                ah[i][0] = *(const uint32_t*)&sAh[r0];
                ah[i][1] = *(const uint32_t*)&sAh[r1];
                ah[i][2] = *(const uint32_t*)&sAh[r0 + 8];
                ah[i][3] = *(const uint32_t*)&sAh[r1 + 8];
                al[i][0] = *(const uint32_t*)&sAl[r0];
                al[i][1] = *(const uint32_t*)&sAl[r1];
                al[i][2] = *(const uint32_t*)&sAl[r0 + 8];
                al[i][3] = *(const uint32_t*)&sAl[r1 + 8];
            }
#pragma unroll
            for (int j = 0; j < NJ; ++j) {
                int nb = (nW + 8 * j + g) * SSTR + ko + 2 * tg;
                uint32_t bh0 = *(const uint32_t*)&sBh[nb];
                uint32_t bh1 = *(const uint32_t*)&sBh[nb + 8];
                uint32_t bl0 = *(const uint32_t*)&sBl[nb];
                uint32_t bl1 = *(const uint32_t*)&sBl[nb + 8];
#pragma unroll
                for (int i = 0; i < 4; ++i) {
                    mma16816(acc[i][j], ah[i][0], ah[i][1], ah[i][2], ah[i][3], bh0, bh1);
                    mma16816(acc[i][j], ah[i][0], ah[i][1], ah[i][2], ah[i][3], bl0, bl1);
                    mma16816(acc[i][j], al[i][0], al[i][1], al[i][2], al[i][3], bh0, bh1);
                }
            }
        }
    }

#pragma unroll
    for (int i = 0; i < 4; ++i) {
        int row0 = rowBase + mW + 16 * i + g;
        int row1 = row0 + 8;
#pragma unroll
        for (int j = 0; j < NJ; ++j) {
            int col = colBase + nW + 8 * j + 2 * tg;
            float2 bb = *(const float2*)(bias + col);
            float2 o0, o1;
            o0.x = fmaxf(acc[i][j][0] + bb.x, 0.f);
            o0.y = fmaxf(acc[i][j][1] + bb.y, 0.f);
            o1.x = fmaxf(acc[i][j][2] + bb.x, 0.f);
            o1.y = fmaxf(acc[i][j][3] + bb.y, 0.f);
            *(float2*)(C + (size_t)row0 * DH + col) = o0;
            *(float2*)(C + (size_t)row1 * DH + col) = o1;
        }
    }
}

// ---------------- final layer: [1024 x 47] logits + log_softmax -------------
__global__ void __launch_bounds__(64)
final_layer(const float* __restrict__ agg, const float* __restrict__ cnt,
            const float* __restrict__ h,
            const float* __restrict__ Wl, const float* __restrict__ Wr,
            const float* __restrict__ bias, float* __restrict__ out)
{
    __shared__ float sA[DH];
    __shared__ float sH[DH];
    __shared__ float sL[DOUT];
    __shared__ float sRed[2];

    int row = blockIdx.x;
    int tid = threadIdx.x;

    float scale = 1.0f / fmaxf(cnt[row], 1.0f);
    for (int i = tid; i < DH; i += 64) {
        sA[i] = agg[(size_t)row * DH + i] * scale;
        sH[i] = h[(size_t)row * DH + i];
    }
    __syncthreads();

    if (tid < DOUT) {
        float accv = bias[tid];
#pragma unroll 8
        for (int k = 0; k < DH; ++k) accv += sA[k] * Wl[k * DOUT + tid];
#pragma unroll 8
        for (int k = 0; k < DH; ++k) accv += sH[k] * Wr[k * DOUT + tid];
        sL[tid] = accv;
    }
    __syncthreads();

    if (tid < 32) {
        float v1 = (tid < DOUT)      ? sL[tid]      : -INFINITY;
        float v2 = (tid + 32 < DOUT) ? sL[tid + 32] : -INFINITY;
        float m = fmaxf(v1, v2);
#pragma unroll
        for (int off = 16; off > 0; off >>= 1)
            m = fmaxf(m, __shfl_xor_sync(0xffffffffu, m, off));
        float s = ((tid < DOUT)      ? expf(v1 - m) : 0.f)
                + ((tid + 32 < DOUT) ? expf(v2 - m) : 0.f);
#pragma unroll
        for (int off = 16; off > 0; off >>= 1)
            s += __shfl_xor_sync(0xffffffffu, s, off);
        if (tid == 0) { sRed[0] = m; sRed[1] = logf(s); }
    }
    __syncthreads();

    if (tid < DOUT)
        out[(size_t)row * DOUT + tid] = sL[tid] - sRed[0] - sRed[1];
}

// ---------------- launch ----------------------------------------------------
extern "C" void kernel_launch(void* const* d_in, const int* in_sizes, int n_in,
                              void* d_out, int out_size) {
    const float* x   = (const float*)d_in[0];
    const float* Wl0 = (const float*)d_in[1];
    const float* Wr0 = (const float*)d_in[2];
    const float* b0  = (const float*)d_in[3];
    const float* Wl1 = (const float*)d_in[4];
    const float* Wr1 = (const float*)d_in[5];
    const float* b1  = (const float*)d_in[6];
    const float* Wl2 = (const float*)d_in[7];
    const float* Wr2 = (const float*)d_in[8];
    const float* b2  = (const float*)d_in[9];
    const int* src0  = (const int*)d_in[10];
    const int* dst0  = (const int*)d_in[11];
    const int* src1  = (const int*)d_in[12];
    const int* dst1  = (const int*)d_in[13];
    const int* src2  = (const int*)d_in[14];
    const int* dst2  = (const int*)d_in[15];
    float* out = (float*)d_out;

    float *agg0, *cnt0, *h1, *agg1, *cnt1, *h2, *agg2, *cnt2;
    ushort_t *wt0h, *wt0l, *wt1h, *wt1l, *Ah0, *Al0, *Ah1, *Al1;
    cudaGetSymbolAddress((void**)&agg0, g_agg0);
    cudaGetSymbolAddress((void**)&cnt0, g_cnt0);
    cudaGetSymbolAddress((void**)&h1,   g_h1);
    cudaGetSymbolAddress((void**)&agg1, g_agg1);
    cudaGetSymbolAddress((void**)&cnt1, g_cnt1);
    cudaGetSymbolAddress((void**)&h2,   g_h2);
    cudaGetSymbolAddress((void**)&agg2, g_agg2);
    cudaGetSymbolAddress((void**)&cnt2, g_cnt2);
    cudaGetSymbolAddress((void**)&wt0h, g_wt0h);
    cudaGetSymbolAddress((void**)&wt0l, g_wt0l);
    cudaGetSymbolAddress((void**)&wt1h, g_wt1h);
    cudaGetSymbolAddress((void**)&wt1l, g_wt1l);
    cudaGetSymbolAddress((void**)&Ah0,  g_Ah0);
    cudaGetSymbolAddress((void**)&Al0,  g_Al0);
    cudaGetSymbolAddress((void**)&Ah1,  g_Ah1);
    cudaGetSymbolAddress((void**)&Al1,  g_Al1);

    const int SMEM0 = (2 * 128 * SSTR + 2 * 256 * SSTR) * 2 * 3;  // 3-stage: 184320B
    const int SMEM1 = (2 * 128 * SSTR + 2 * 128 * SSTR) * 2 * 3;  // 3-stage: 122880B
    cudaFuncSetAttribute(gemm3p<256, 256>, cudaFuncAttributeMaxDynamicSharedMemorySize, SMEM0);
    cudaFuncSetAttribute(gemm3p<512, 128>, cudaFuncAttributeMaxDynamicSharedMemorySize, SMEM1);

    // ---- layer 0 ----
    build_wt_split<<<(256 * 256 + 255) / 256, 256>>>(Wl0, Wr0, wt0h, wt0l, DIN, 256);
    zero_agg<<<(N1c * (DIN/4) + 255) / 256, 256>>>((float4*)agg0, cnt0, N1c * (DIN/4), N1c);
    scatter_x4<<<E0c / 32, 256>>>(src0, dst0, x, agg0, cnt0, E0c);
    split_A<<<(N1c * 32 + 255) / 256, 256>>>(agg0, cnt0, x, Ah0, Al0, DIN, DIN, N1c);
    gemm3p<256, 256><<<dim3(N1c / 128, 1), 256, SMEM0>>>(Ah0, Al0, wt0h, wt0l, b0, h1);

    // ---- layer 1 ----
    build_wt_split<<<(256 * 512 + 255) / 256, 256>>>(Wl1, Wr1, wt1h, wt1l, DH, 512);
    zero_agg<<<(N2c * (DH/4) + 255) / 256, 256>>>((float4*)agg1, cnt1, N2c * (DH/4), N2c);
    scatter_h4<<<E1c / 32, 256>>>(src1, dst1, h1, agg1, cnt1, E1c);
    split_A<<<(N2c * 64 + 255) / 256, 256>>>(agg1, cnt1, h1, Ah1, Al1, DH, DH, N2c);
    gemm3p<512, 128><<<dim3(N2c / 128, 2), 256, SMEM1>>>(Ah1, Al1, wt1h, wt1l, b1, h2);

    // ---- layer 2 ----
    zero_agg<<<(N3c * (DH/4) + 255) / 256, 256>>>((float4*)agg2, cnt2, N3c * (DH/4), N3c);
    scatter_h4<<<E2c / 32, 256>>>(src2, dst2, h2, agg2, cnt2, E2c);
    final_layer<<<N3c, 64>>>(agg2, cnt2, h2, Wl2, Wr2, b2, out);
}

// round 12
// speedup vs baseline: 1.8144x; 1.1603x over previous
#include <cuda_runtime.h>
#include <cuda_bf16.h>
#include <math.h>
#include <stdint.h>

#define N0c  1982464
#define N1c  123904
#define N2c  11264
#define N3c  1024
#define E0c  1858560
#define E1c  112640
#define E2c  10240
#define DIN  128
#define DH   256
#define DOUT 47

typedef unsigned short ushort_t;

// ---------------- scratch ---------------------------------------------------
__device__ float g_h1[(size_t)N1c * DH];
__device__ float g_h2[(size_t)N2c * DH];
__device__ float g_agg2[(size_t)N3c * DH];
__device__ float g_cnt2[N3c];
__device__ ushort_t g_wt0h[256 * 256];
__device__ ushort_t g_wt0l[256 * 256];
__device__ ushort_t g_wt1h[256 * 512];
__device__ ushort_t g_wt1l[256 * 512];
__device__ ushort_t g_Ah0[(size_t)N1c * 256];
__device__ ushort_t g_Al0[(size_t)N1c * 256];
__device__ ushort_t g_Ah1[(size_t)N2c * 512];
__device__ ushort_t g_Al1[(size_t)N2c * 512];
// sort scratch (layer 0 sizes dominate)
__device__ int g_icnt[N1c];
__device__ int g_off[N1c + 1];
__device__ int g_cur[N1c];
__device__ int g_part[1024];
__device__ int g_ssrc[E0c];
// layer-1 sort scratch
__device__ int g_icnt1[N2c];
__device__ int g_off1[N2c + 1];
__device__ int g_cur1[N2c];
__device__ int g_part1[1024];
__device__ int g_ssrc1[E1c];

// ---------------- zero ------------------------------------------------------
__global__ void zero_agg(float4* agg4, float* cnt, int n4, int ncnt) {
    int i = blockIdx.x * blockDim.x + threadIdx.x;
    if (i < n4)   agg4[i] = make_float4(0.f, 0.f, 0.f, 0.f);
    if (i < ncnt) cnt[i]  = 0.f;
}
__global__ void zero_int(int* p, int n) {
    int i = blockIdx.x * blockDim.x + threadIdx.x;
    if (i < n) p[i] = 0;
}

// ---------------- counting sort by dst --------------------------------------
__global__ void hist_k(const int* __restrict__ dst, int* __restrict__ c, int E) {
    int i = blockIdx.x * blockDim.x + threadIdx.x;
    if (i < E) atomicAdd(c + dst[i], 1);
}
// per-1024-block exclusive scan + block totals
__global__ void scan_block(const int* __restrict__ c, int* __restrict__ off,
                           int* __restrict__ partial, int n) {
    __shared__ int sm[1024];
    int gid = blockIdx.x * 1024 + threadIdx.x;
    int v = (gid < n) ? c[gid] : 0;
    sm[threadIdx.x] = v;
    __syncthreads();
    for (int o = 1; o < 1024; o <<= 1) {
        int t = (threadIdx.x >= o) ? sm[threadIdx.x - o] : 0;
        __syncthreads();
        sm[threadIdx.x] += t;
        __syncthreads();
    }
    if (gid < n) off[gid] = sm[threadIdx.x] - v;       // exclusive
    if (threadIdx.x == 1023) partial[blockIdx.x] = sm[1023];
}
__global__ void scan_partials(int* partial, int np) {
    __shared__ int sm[1024];
    int v = (threadIdx.x < np) ? partial[threadIdx.x] : 0;
    sm[threadIdx.x] = v;
    __syncthreads();
    for (int o = 1; o < 1024; o <<= 1) {
        int t = (threadIdx.x >= o) ? sm[threadIdx.x - o] : 0;
        __syncthreads();
        sm[threadIdx.x] += t;
        __syncthreads();
    }
    if (threadIdx.x < np) partial[threadIdx.x] = sm[threadIdx.x] - v;  // exclusive
}
__global__ void scan_add(int* __restrict__ off, const int* __restrict__ partial,
                         int* __restrict__ cur, int n, int E) {
    int gid = blockIdx.x * blockDim.x + threadIdx.x;
    if (gid < n) {
        int o = off[gid] + partial[gid >> 10];
        off[gid] = o;
        cur[gid] = o;
    }
    if (gid == 0) off[n] = E;
}
__global__ void sort_scatter(const int* __restrict__ src, const int* __restrict__ dst,
                             int* __restrict__ cur, int* __restrict__ ssrc, int E) {
    int e = blockIdx.x * blockDim.x + threadIdx.x;
    if (e < E) {
        int p = atomicAdd(cur + dst[e], 1);
        ssrc[p] = src[e];
    }
}

// ---------------- segment aggregate + normalize + bf16-split ----------------
// One warp per target row. A = [mean(gather) | self], K = 2*D, bf16 hi/lo out.
__device__ __forceinline__ void split_store(ushort_t* ph, ushort_t* pl, float4 v) {
    ushort_t hs[4], ls[4];
    float f[4] = {v.x, v.y, v.z, v.w};
#pragma unroll
    for (int i = 0; i < 4; ++i) {
        __nv_bfloat16 hb = __float2bfloat16(f[i]);
        __nv_bfloat16 lb = __float2bfloat16(f[i] - __bfloat162float(hb));
        hs[i] = __bfloat16_as_ushort(hb);
        ls[i] = __bfloat16_as_ushort(lb);
    }
    *(uint2*)ph = *(uint2*)hs;
    *(uint2*)pl = *(uint2*)ls;
}

template<int D>
__global__ void __launch_bounds__(256)
agg_split(const int* __restrict__ ssrc, const int* __restrict__ off,
          const float* __restrict__ xs, const float* __restrict__ xself,
          ushort_t* __restrict__ Ah, ushort_t* __restrict__ Al, int M)
{
    constexpr int K = 2 * D;
    constexpr int V = D / 128;   // float4s per lane (1 or 2)
    int w    = (blockIdx.x * blockDim.x + threadIdx.x) >> 5;
    int lane = threadIdx.x & 31;
    if (w >= M) return;
    int s = off[w], e = off[w + 1];

    float4 acc[V];
#pragma unroll
    for (int v = 0; v < V; ++v) acc[v] = make_float4(0.f, 0.f, 0.f, 0.f);

    int i = s;
    for (; i + 4 <= e; i += 4) {
        int i0 = __ldg(ssrc + i),     i1 = __ldg(ssrc + i + 1);
        int i2 = __ldg(ssrc + i + 2), i3 = __ldg(ssrc + i + 3);
        const float4* r0 = (const float4*)(xs + (size_t)i0 * D);
        const float4* r1 = (const float4*)(xs + (size_t)i1 * D);
        const float4* r2 = (const float4*)(xs + (size_t)i2 * D);
        const float4* r3 = (const float4*)(xs + (size_t)i3 * D);
#pragma unroll
        for (int v = 0; v < V; ++v) {
            float4 a = r0[lane + 32 * v];
            float4 b = r1[lane + 32 * v];
            float4 c = r2[lane + 32 * v];
            float4 d = r3[lane + 32 * v];
            acc[v].x += (a.x + b.x) + (c.x + d.x);
            acc[v].y += (a.y + b.y) + (c.y + d.y);
            acc[v].z += (a.z + b.z) + (c.z + d.z);
            acc[v].w += (a.w + b.w) + (c.w + d.w);
        }
    }
    for (; i < e; ++i) {
        int i0 = __ldg(ssrc + i);
        const float4* r0 = (const float4*)(xs + (size_t)i0 * D);
#pragma unroll
        for (int v = 0; v < V; ++v) {
            float4 a = r0[lane + 32 * v];
            acc[v].x += a.x; acc[v].y += a.y; acc[v].z += a.z; acc[v].w += a.w;
        }
    }

    float sc = 1.0f / fmaxf((float)(e - s), 1.0f);
    ushort_t* rh = Ah + (size_t)w * K;
    ushort_t* rl = Al + (size_t)w * K;
#pragma unroll
    for (int v = 0; v < V; ++v) {
        float4 m = acc[v];
        m.x *= sc; m.y *= sc; m.z *= sc; m.w *= sc;
        split_store(rh + (lane + 32 * v) * 4, rl + (lane + 32 * v) * 4, m);
    }
    // self half
    const float4* sr = (const float4*)(xself + (size_t)w * D);
#pragma unroll
    for (int v = 0; v < V; ++v) {
        float4 m = sr[lane + 32 * v];
        split_store(rh + D + (lane + 32 * v) * 4, rl + D + (lane + 32 * v) * 4, m);
    }
}

// ---------------- scatter (layer 2 only, tiny) ------------------------------
__device__ __forceinline__ void red_v4(float* p, float4 v) {
    asm volatile("red.global.add.v4.f32 [%0], {%1,%2,%3,%4};"
                 :: "l"(p), "f"(v.x), "f"(v.y), "f"(v.z), "f"(v.w) : "memory");
}
__global__ void scatter_h4(const int* __restrict__ src, const int* __restrict__ dst,
                           const float* __restrict__ h, float* __restrict__ agg,
                           float* __restrict__ cnt, int E) {
    int w    = (blockIdx.x * blockDim.x + threadIdx.x) >> 5;
    int lane = threadIdx.x & 31;
    int e0 = w * 4;
    if (e0 >= E) return;
    int4 s4 = *(const int4*)(src + e0);
    int4 d4 = *(const int4*)(dst + e0);
    const float4* r0 = (const float4*)(h + (size_t)s4.x * DH);
    const float4* r1 = (const float4*)(h + (size_t)s4.y * DH);
    const float4* r2 = (const float4*)(h + (size_t)s4.z * DH);
    const float4* r3 = (const float4*)(h + (size_t)s4.w * DH);
    float4 a0 = r0[lane], b0 = r0[lane + 32];
    float4 a1 = r1[lane], b1 = r1[lane + 32];
    float4 a2 = r2[lane], b2 = r2[lane + 32];
    float4 a3 = r3[lane], b3 = r3[lane + 32];
    red_v4(agg + (size_t)d4.x * DH + lane * 4, a0);
    red_v4(agg + (size_t)d4.x * DH + (lane + 32) * 4, b0);
    red_v4(agg + (size_t)d4.y * DH + lane * 4, a1);
    red_v4(agg + (size_t)d4.y * DH + (lane + 32) * 4, b1);
    red_v4(agg + (size_t)d4.z * DH + lane * 4, a2);
    red_v4(agg + (size_t)d4.z * DH + (lane + 32) * 4, b2);
    red_v4(agg + (size_t)d4.w * DH + lane * 4, a3);
    red_v4(agg + (size_t)d4.w * DH + (lane + 32) * 4, b3);
    if (lane < 4) {
        int d = (lane == 0) ? d4.x : (lane == 1) ? d4.y : (lane == 2) ? d4.z : d4.w;
        atomicAdd(cnt + d, 1.0f);
    }
}

// ---------------- weight prep: split bf16, transposed [n][k] ----------------
__global__ void build_wt_split(const float* __restrict__ Wl, const float* __restrict__ Wr,
                               ushort_t* __restrict__ WtH,
                               ushort_t* __restrict__ WtL, int KA, int K) {
    int idx = blockIdx.x * blockDim.x + threadIdx.x;
    if (idx >= 256 * K) return;
    int n = idx / K, k = idx % K;
    float w = (k < KA) ? Wl[(size_t)k * DH + n] : Wr[(size_t)(k - KA) * DH + n];
    __nv_bfloat16 hi = __float2bfloat16(w);
    __nv_bfloat16 lo = __float2bfloat16(w - __bfloat162float(hi));
    WtH[idx] = __bfloat16_as_ushort(hi);
    WtL[idx] = __bfloat16_as_ushort(lo);
}

// ---------------- mma.sync bf16 helpers -------------------------------------
__device__ __forceinline__ void mma16816(float* c, uint32_t a0, uint32_t a1,
                                         uint32_t a2, uint32_t a3,
                                         uint32_t b0, uint32_t b1) {
    asm volatile(
        "mma.sync.aligned.m16n8k16.row.col.f32.bf16.bf16.f32 "
        "{%0,%1,%2,%3}, {%4,%5,%6,%7}, {%8,%9}, {%0,%1,%2,%3};"
        : "+f"(c[0]), "+f"(c[1]), "+f"(c[2]), "+f"(c[3])
        : "r"(a0), "r"(a1), "r"(a2), "r"(a3), "r"(b0), "r"(b1));
}
__device__ __forceinline__ void cpa16(uint32_t dst, const void* src) {
    asm volatile("cp.async.ca.shared.global [%0], [%1], 16;" :: "r"(dst), "l"(src));
}

// ---------------- 3-stage pipelined bf16-split tensor-core GEMM -------------
#define SSTR 40
template<int K, int BN>
__global__ void __launch_bounds__(256)
gemm3p(const ushort_t* __restrict__ Ah, const ushort_t* __restrict__ Al,
       const ushort_t* __restrict__ WtH, const ushort_t* __restrict__ WtL,
       const float* __restrict__ bias, float* __restrict__ C)
{
    extern __shared__ ushort_t sm[];
    constexpr int ASZ = 128 * SSTR;
    constexpr int BSZ = BN * SSTR;
    constexpr int STG = 2 * ASZ + 2 * BSZ;
    constexpr int WN  = BN / 4;
    constexpr int NJ  = WN / 8;
    constexpr int NCH = K / 32;
    constexpr int BCH = BN * 4 / 256;

    const int tid  = threadIdx.x;
    const int w    = tid >> 5;
    const int lane = tid & 31;
    const int g    = lane >> 2;
    const int tg   = lane & 3;

    const int rowBase = blockIdx.x * 128;
    const int colBase = blockIdx.y * BN;
    const int mW = (w >> 2) * 64;
    const int nW = (w & 3) * WN;

    const uint32_t smB = (uint32_t)__cvta_generic_to_shared(sm);

    float acc[4][NJ][4];
#pragma unroll
    for (int i = 0; i < 4; i++)
#pragma unroll
        for (int j = 0; j < NJ; j++)
#pragma unroll
            for (int q = 0; q < 4; q++) acc[i][j][q] = 0.f;

    auto load_stage = [&](int c, int buf) {
        const int kb = c * 32;
        const uint32_t sb = smB + (uint32_t)buf * STG * 2;
#pragma unroll
        for (int t = 0; t < 2; ++t) {
            int chunk = tid + t * 256;
            int row = chunk >> 2, c4 = chunk & 3;
            uint32_t d = sb + (uint32_t)(row * SSTR + c4 * 8) * 2;
            const size_t go = (size_t)(rowBase + row) * K + kb + c4 * 8;
            cpa16(d,           Ah + go);
            cpa16(d + ASZ * 2, Al + go);
        }
#pragma unroll
        for (int t = 0; t < BCH; ++t) {
            int chunk = tid + t * 256;
            int row = chunk >> 2, c4 = chunk & 3;
            uint32_t d = sb + (uint32_t)(2 * ASZ + row * SSTR + c4 * 8) * 2;
            const size_t go = (size_t)(colBase + row) * K + kb + c4 * 8;
            cpa16(d,           WtH + go);
            cpa16(d + BSZ * 2, WtL + go);
        }
        asm volatile("cp.async.commit_group;" ::: "memory");
    };

    load_stage(0, 0);
    if (NCH > 1) load_stage(1, 1);

    for (int c = 0; c < NCH; ++c) {
        if (c + 1 < NCH) asm volatile("cp.async.wait_group 1;" ::: "memory");
        else             asm volatile("cp.async.wait_group 0;" ::: "memory");
        __syncthreads();
        if (c + 2 < NCH) load_stage(c + 2, (c + 2) % 3);

        const ushort_t* sAh = sm + (c % 3) * STG;
        const ushort_t* sAl = sAh + ASZ;
        const ushort_t* sBh = sAh + 2 * ASZ;
        const ushort_t* sBl = sBh + BSZ;

#pragma unroll
        for (int ks = 0; ks < 2; ++ks) {
            const int ko = ks * 16;
            uint32_t ah[4][4], al[4][4];
#pragma unroll
            for (int i = 0; i < 4; ++i) {
                int r0 = (mW + 16 * i + g) * SSTR + ko + 2 * tg;
                int r1 = r0 + 8 * SSTR;
                ah[i][0] = *(const uint32_t*)&sAh[r0];
                ah[i][1] = *(const uint32_t*)&sAh[r1];
                ah[i][2] = *(const uint32_t*)&sAh[r0 + 8];
                ah[i][3] = *(const uint32_t*)&sAh[r1 + 8];
                al[i][0] = *(const uint32_t*)&sAl[r0];
                al[i][1] = *(const uint32_t*)&sAl[r1];
                al[i][2] = *(const uint32_t*)&sAl[r0 + 8];
                al[i][3] = *(const uint32_t*)&sAl[r1 + 8];
            }
#pragma unroll
            for (int j = 0; j < NJ; ++j) {
                int nb = (nW + 8 * j + g) * SSTR + ko + 2 * tg;
                uint32_t bh0 = *(const uint32_t*)&sBh[nb];
                uint32_t bh1 = *(const uint32_t*)&sBh[nb + 8];
                uint32_t bl0 = *(const uint32_t*)&sBl[nb];
                uint32_t bl1 = *(const uint32_t*)&sBl[nb + 8];
#pragma unroll
                for (int i = 0; i < 4; ++i) {
                    mma16816(acc[i][j], ah[i][0], ah[i][1], ah[i][2], ah[i][3], bh0, bh1);
                    mma16816(acc[i][j], ah[i][0], ah[i][1], ah[i][2], ah[i][3], bl0, bl1);
                    mma16816(acc[i][j], al[i][0], al[i][1], al[i][2], al[i][3], bh0, bh1);
                }
            }
        }
    }

#pragma unroll
    for (int i = 0; i < 4; ++i) {
        int row0 = rowBase + mW + 16 * i + g;
        int row1 = row0 + 8;
#pragma unroll
        for (int j = 0; j < NJ; ++j) {
            int col = colBase + nW + 8 * j + 2 * tg;
            float2 bb = *(const float2*)(bias + col);
            float2 o0, o1;
            o0.x = fmaxf(acc[i][j][0] + bb.x, 0.f);
            o0.y = fmaxf(acc[i][j][1] + bb.y, 0.f);
            o1.x = fmaxf(acc[i][j][2] + bb.x, 0.f);
            o1.y = fmaxf(acc[i][j][3] + bb.y, 0.f);
            *(float2*)(C + (size_t)row0 * DH + col) = o0;
            *(float2*)(C + (size_t)row1 * DH + col) = o1;
        }
    }
}

// ---------------- final layer: [1024 x 47] logits + log_softmax -------------
__global__ void __launch_bounds__(64)
final_layer(const float* __restrict__ agg, const float* __restrict__ cnt,
            const float* __restrict__ h,
            const float* __restrict__ Wl, const float* __restrict__ Wr,
            const float* __restrict__ bias, float* __restrict__ out)
{
    __shared__ float sA[DH];
    __shared__ float sH[DH];
    __shared__ float sL[DOUT];
    __shared__ float sRed[2];

    int row = blockIdx.x;
    int tid = threadIdx.x;

    float scale = 1.0f / fmaxf(cnt[row], 1.0f);
    for (int i = tid; i < DH; i += 64) {
        sA[i] = agg[(size_t)row * DH + i] * scale;
        sH[i] = h[(size_t)row * DH + i];
    }
    __syncthreads();

    if (tid < DOUT) {
        float accv = bias[tid];
#pragma unroll 8
        for (int k = 0; k < DH; ++k) accv += sA[k] * Wl[k * DOUT + tid];
#pragma unroll 8
        for (int k = 0; k < DH; ++k) accv += sH[k] * Wr[k * DOUT + tid];
        sL[tid] = accv;
    }
    __syncthreads();

    if (tid < 32) {
        float v1 = (tid < DOUT)      ? sL[tid]      : -INFINITY;
        float v2 = (tid + 32 < DOUT) ? sL[tid + 32] : -INFINITY;
        float m = fmaxf(v1, v2);
#pragma unroll
        for (int off = 16; off > 0; off >>= 1)
            m = fmaxf(m, __shfl_xor_sync(0xffffffffu, m, off));
        float s = ((tid < DOUT)      ? expf(v1 - m) : 0.f)
                + ((tid + 32 < DOUT) ? expf(v2 - m) : 0.f);
#pragma unroll
        for (int off = 16; off > 0; off >>= 1)
            s += __shfl_xor_sync(0xffffffffu, s, off);
        if (tid == 0) { sRed[0] = m; sRed[1] = logf(s); }
    }
    __syncthreads();

    if (tid < DOUT)
        out[(size_t)row * DOUT + tid] = sL[tid] - sRed[0] - sRed[1];
}

// ---------------- launch ----------------------------------------------------
extern "C" void kernel_launch(void* const* d_in, const int* in_sizes, int n_in,
                              void* d_out, int out_size) {
    const float* x   = (const float*)d_in[0];
    const float* Wl0 = (const float*)d_in[1];
    const float* Wr0 = (const float*)d_in[2];
    const float* b0  = (const float*)d_in[3];
    const float* Wl1 = (const float*)d_in[4];
    const float* Wr1 = (const float*)d_in[5];
    const float* b1  = (const float*)d_in[6];
    const float* Wl2 = (const float*)d_in[7];
    const float* Wr2 = (const float*)d_in[8];
    const float* b2  = (const float*)d_in[9];
    const int* src0  = (const int*)d_in[10];
    const int* dst0  = (const int*)d_in[11];
    const int* src1  = (const int*)d_in[12];
    const int* dst1  = (const int*)d_in[13];
    const int* src2  = (const int*)d_in[14];
    const int* dst2  = (const int*)d_in[15];
    float* out = (float*)d_out;

    float *h1, *h2, *agg2, *cnt2;
    ushort_t *wt0h, *wt0l, *wt1h, *wt1l, *Ah0, *Al0, *Ah1, *Al1;
    int *icnt, *off, *cur, *part, *ssrc;
    int *icnt1, *off1, *cur1, *part1, *ssrc1;
    cudaGetSymbolAddress((void**)&h1,    g_h1);
    cudaGetSymbolAddress((void**)&h2,    g_h2);
    cudaGetSymbolAddress((void**)&agg2,  g_agg2);
    cudaGetSymbolAddress((void**)&cnt2,  g_cnt2);
    cudaGetSymbolAddress((void**)&wt0h,  g_wt0h);
    cudaGetSymbolAddress((void**)&wt0l,  g_wt0l);
    cudaGetSymbolAddress((void**)&wt1h,  g_wt1h);
    cudaGetSymbolAddress((void**)&wt1l,  g_wt1l);
    cudaGetSymbolAddress((void**)&Ah0,   g_Ah0);
    cudaGetSymbolAddress((void**)&Al0,   g_Al0);
    cudaGetSymbolAddress((void**)&Ah1,   g_Ah1);
    cudaGetSymbolAddress((void**)&Al1,   g_Al1);
    cudaGetSymbolAddress((void**)&icnt,  g_icnt);
    cudaGetSymbolAddress((void**)&off,   g_off);
    cudaGetSymbolAddress((void**)&cur,   g_cur);
    cudaGetSymbolAddress((void**)&part,  g_part);
    cudaGetSymbolAddress((void**)&ssrc,  g_ssrc);
    cudaGetSymbolAddress((void**)&icnt1, g_icnt1);
    cudaGetSymbolAddress((void**)&off1,  g_off1);
    cudaGetSymbolAddress((void**)&cur1,  g_cur1);
    cudaGetSymbolAddress((void**)&part1, g_part1);
    cudaGetSymbolAddress((void**)&ssrc1, g_ssrc1);

    const int SMEM0 = (2 * 128 * SSTR + 2 * 256 * SSTR) * 2 * 3;  // 184320
    const int SMEM1 = (2 * 128 * SSTR + 2 * 128 * SSTR) * 2 * 3;  // 122880
    cudaFuncSetAttribute(gemm3p<256, 256>, cudaFuncAttributeMaxDynamicSharedMemorySize, SMEM0);
    cudaFuncSetAttribute(gemm3p<512, 128>, cudaFuncAttributeMaxDynamicSharedMemorySize, SMEM1);

    const int NB0 = (N1c + 1023) / 1024;   // 121
    const int NB1 = (N2c + 1023) / 1024;   // 11

    // ---- layer 0: sort by dst, aggregate, gemm ----
    build_wt_split<<<(256 * 256 + 255) / 256, 256>>>(Wl0, Wr0, wt0h, wt0l, DIN, 256);
    zero_int<<<(N1c + 255) / 256, 256>>>(icnt, N1c);
    hist_k<<<(E0c + 255) / 256, 256>>>(dst0, icnt, E0c);
    scan_block<<<NB0, 1024>>>(icnt, off, part, N1c);
    scan_partials<<<1, 1024>>>(part, NB0);
    scan_add<<<(N1c + 255) / 256, 256>>>(off, part, cur, N1c, E0c);
    sort_scatter<<<(E0c + 255) / 256, 256>>>(src0, dst0, cur, ssrc, E0c);
    agg_split<DIN><<<(N1c + 7) / 8, 256>>>(ssrc, off, x, x, Ah0, Al0, N1c);
    gemm3p<256, 256><<<dim3(N1c / 128, 1), 256, SMEM0>>>(Ah0, Al0, wt0h, wt0l, b0, h1);

    // ---- layer 1 ----
    build_wt_split<<<(256 * 512 + 255) / 256, 256>>>(Wl1, Wr1, wt1h, wt1l, DH, 512);
    zero_int<<<(N2c + 255) / 256, 256>>>(icnt1, N2c);
    hist_k<<<(E1c + 255) / 256, 256>>>(dst1, icnt1, E1c);
    scan_block<<<NB1, 1024>>>(icnt1, off1, part1, N2c);
    scan_partials<<<1, 1024>>>(part1, NB1);
    scan_add<<<(N2c + 255) / 256, 256>>>(off1, part1, cur1, N2c, E1c);
    sort_scatter<<<(E1c + 255) / 256, 256>>>(src1, dst1, cur1, ssrc1, E1c);
    agg_split<DH><<<(N2c + 7) / 8, 256>>>(ssrc1, off1, h1, h1, Ah1, Al1, N2c);
    gemm3p<512, 128><<<dim3(N2c / 128, 2), 256, SMEM1>>>(Ah1, Al1, wt1h, wt1l, b1, h2);

    // ---- layer 2 (tiny; atomic path) ----
    zero_agg<<<(N3c * (DH/4) + 255) / 256, 256>>>((float4*)agg2, cnt2, N3c * (DH/4), N3c);
    scatter_h4<<<E2c / 32, 256>>>(src2, dst2, h2, agg2, cnt2, E2c);
    final_layer<<<N3c, 64>>>(agg2, cnt2, h2, Wl2, Wr2, b2, out);
}

// round 15
// speedup vs baseline: 2.0850x; 1.1492x over previous
#include <cuda_runtime.h>
#include <cuda_fp16.h>
#include <math.h>
#include <stdint.h>

#define N0c  1982464
#define N1c  123904
#define N2c  11264
#define N3c  1024
#define E0c  1858560
#define E1c  112640
#define E2c  10240
#define DIN  128
#define DH   256
#define DOUT 47

typedef unsigned short ushort_t;

// ---------------- scratch ---------------------------------------------------
__device__ float g_h1[(size_t)N1c * DH];
__device__ float g_h2[(size_t)N2c * DH];
__device__ float g_agg2[(size_t)N3c * DH];
__device__ float g_cnt2[N3c];
__device__ ushort_t g_wt0h[256 * 256];   // fp16 hi weights [n][k]
__device__ ushort_t g_wt1h[256 * 512];
__device__ ushort_t g_Ah0[(size_t)N1c * 256];   // fp16 hi/lo A
__device__ ushort_t g_Al0[(size_t)N1c * 256];
__device__ ushort_t g_Ah1[(size_t)N2c * 512];
__device__ ushort_t g_Al1[(size_t)N2c * 512];
// sort scratch
__device__ int g_icnt[N1c];
__device__ int g_off[N1c + 1];
__device__ int g_cur[N1c];
__device__ int g_part[1024];
__device__ int g_ssrc[E0c];
__device__ int g_icnt1[N2c];
__device__ int g_off1[N2c + 1];
__device__ int g_cur1[N2c];
__device__ int g_part1[1024];
__device__ int g_ssrc1[E1c];

// ---------------- zero ------------------------------------------------------
__global__ void zero_agg(float4* agg4, float* cnt, int n4, int ncnt) {
    int i = blockIdx.x * blockDim.x + threadIdx.x;
    if (i < n4)   agg4[i] = make_float4(0.f, 0.f, 0.f, 0.f);
    if (i < ncnt) cnt[i]  = 0.f;
}
__global__ void zero_int(int* p, int n) {
    int i = blockIdx.x * blockDim.x + threadIdx.x;
    if (i < n) p[i] = 0;
}

// ---------------- counting sort by dst --------------------------------------
__global__ void hist_k(const int* __restrict__ dst, int* __restrict__ c, int E) {
    int i = blockIdx.x * blockDim.x + threadIdx.x;
    if (i < E) atomicAdd(c + dst[i], 1);
}
__global__ void scan_block(const int* __restrict__ c, int* __restrict__ off,
                           int* __restrict__ partial, int n) {
    __shared__ int sm[1024];
    int gid = blockIdx.x * 1024 + threadIdx.x;
    int v = (gid < n) ? c[gid] : 0;
    sm[threadIdx.x] = v;
    __syncthreads();
    for (int o = 1; o < 1024; o <<= 1) {
        int t = (threadIdx.x >= o) ? sm[threadIdx.x - o] : 0;
        __syncthreads();
        sm[threadIdx.x] += t;
        __syncthreads();
    }
    if (gid < n) off[gid] = sm[threadIdx.x] - v;
    if (threadIdx.x == 1023) partial[blockIdx.x] = sm[1023];
}
__global__ void scan_partials(int* partial, int np) {
    __shared__ int sm[1024];
    int v = (threadIdx.x < np) ? partial[threadIdx.x] : 0;
    sm[threadIdx.x] = v;
    __syncthreads();
    for (int o = 1; o < 1024; o <<= 1) {
        int t = (threadIdx.x >= o) ? sm[threadIdx.x - o] : 0;
        __syncthreads();
        sm[threadIdx.x] += t;
        __syncthreads();
    }
    if (threadIdx.x < np) partial[threadIdx.x] = sm[threadIdx.x] - v;
}
__global__ void scan_add(int* __restrict__ off, const int* __restrict__ partial,
                         int* __restrict__ cur, int n, int E) {
    int gid = blockIdx.x * blockDim.x + threadIdx.x;
    if (gid < n) {
        int o = off[gid] + partial[gid >> 10];
        off[gid] = o;
        cur[gid] = o;
    }
    if (gid == 0) off[n] = E;
}
__global__ void sort_scatter(const int* __restrict__ src, const int* __restrict__ dst,
                             int* __restrict__ cur, int* __restrict__ ssrc, int E) {
    int e = blockIdx.x * blockDim.x + threadIdx.x;
    if (e < E) {
        int p = atomicAdd(cur + dst[e], 1);
        ssrc[p] = src[e];
    }
}

// ---------------- segment aggregate + normalize + fp16-split ----------------
__device__ __forceinline__ void split_store(ushort_t* ph, ushort_t* pl, float4 v) {
    ushort_t hs[4], ls[4];
    float f[4] = {v.x, v.y, v.z, v.w};
#pragma unroll
    for (int i = 0; i < 4; ++i) {
        __half hb = __float2half_rn(f[i]);
        __half lb = __float2half_rn(f[i] - __half2float(hb));
        hs[i] = __half_as_ushort(hb);
        ls[i] = __half_as_ushort(lb);
    }
    *(uint2*)ph = *(uint2*)hs;
    *(uint2*)pl = *(uint2*)ls;
}

// BATCH = independent gathers in flight per warp (MLP knob)
template<int D, int BATCH>
__global__ void __launch_bounds__(256)
agg_split(const int* __restrict__ ssrc, const int* __restrict__ off,
          const float* __restrict__ xs, const float* __restrict__ xself,
          ushort_t* __restrict__ Ah, ushort_t* __restrict__ Al, int M)
{
    constexpr int K = 2 * D;
    constexpr int V = D / 128;
    int w    = (blockIdx.x * blockDim.x + threadIdx.x) >> 5;
    int lane = threadIdx.x & 31;
    if (w >= M) return;
    int s = off[w], e = off[w + 1];

    float4 acc[V];
#pragma unroll
    for (int v = 0; v < V; ++v) acc[v] = make_float4(0.f, 0.f, 0.f, 0.f);

    int i = s;
    for (; i + BATCH <= e; i += BATCH) {
        int idx[BATCH];
#pragma unroll
        for (int b = 0; b < BATCH; ++b) idx[b] = __ldg(ssrc + i + b);
        float4 vv[BATCH][V];
#pragma unroll
        for (int b = 0; b < BATCH; ++b) {
            const float4* r = (const float4*)(xs + (size_t)idx[b] * D);
#pragma unroll
            for (int v = 0; v < V; ++v) vv[b][v] = r[lane + 32 * v];
        }
#pragma unroll
        for (int b = 0; b < BATCH; ++b)
#pragma unroll
            for (int v = 0; v < V; ++v) {
                acc[v].x += vv[b][v].x; acc[v].y += vv[b][v].y;
                acc[v].z += vv[b][v].z; acc[v].w += vv[b][v].w;
            }
    }
    for (; i < e; ++i) {
        int i0 = __ldg(ssrc + i);
        const float4* r0 = (const float4*)(xs + (size_t)i0 * D);
#pragma unroll
        for (int v = 0; v < V; ++v) {
            float4 a = r0[lane + 32 * v];
            acc[v].x += a.x; acc[v].y += a.y; acc[v].z += a.z; acc[v].w += a.w;
        }
    }

    float sc = 1.0f / fmaxf((float)(e - s), 1.0f);
    ushort_t* rh = Ah + (size_t)w * K;
    ushort_t* rl = Al + (size_t)w * K;
#pragma unroll
    for (int v = 0; v < V; ++v) {
        float4 m = acc[v];
        m.x *= sc; m.y *= sc; m.z *= sc; m.w *= sc;
        split_store(rh + (lane + 32 * v) * 4, rl + (lane + 32 * v) * 4, m);
    }
    const float4* sr = (const float4*)(xself + (size_t)w * D);
#pragma unroll
    for (int v = 0; v < V; ++v) {
        float4 m = sr[lane + 32 * v];
        split_store(rh + D + (lane + 32 * v) * 4, rl + D + (lane + 32 * v) * 4, m);
    }
}

// ---------------- scatter (layer 2 only, tiny) ------------------------------
__device__ __forceinline__ void red_v4(float* p, float4 v) {
    asm volatile("red.global.add.v4.f32 [%0], {%1,%2,%3,%4};"
                 :: "l"(p), "f"(v.x), "f"(v.y), "f"(v.z), "f"(v.w) : "memory");
}
__global__ void scatter_h4(const int* __restrict__ src, const int* __restrict__ dst,
                           const float* __restrict__ h, float* __restrict__ agg,
                           float* __restrict__ cnt, int E) {
    int w    = (blockIdx.x * blockDim.x + threadIdx.x) >> 5;
    int lane = threadIdx.x & 31;
    int e0 = w * 4;
    if (e0 >= E) return;
    int4 s4 = *(const int4*)(src + e0);
    int4 d4 = *(const int4*)(dst + e0);
    const float4* r0 = (const float4*)(h + (size_t)s4.x * DH);
    const float4* r1 = (const float4*)(h + (size_t)s4.y * DH);
    const float4* r2 = (const float4*)(h + (size_t)s4.z * DH);
    const float4* r3 = (const float4*)(h + (size_t)s4.w * DH);
    float4 a0 = r0[lane], b0 = r0[lane + 32];
    float4 a1 = r1[lane], b1 = r1[lane + 32];
    float4 a2 = r2[lane], b2 = r2[lane + 32];
    float4 a3 = r3[lane], b3 = r3[lane + 32];
    red_v4(agg + (size_t)d4.x * DH + lane * 4, a0);
    red_v4(agg + (size_t)d4.x * DH + (lane + 32) * 4, b0);
    red_v4(agg + (size_t)d4.y * DH + lane * 4, a1);
    red_v4(agg + (size_t)d4.y * DH + (lane + 32) * 4, b1);
    red_v4(agg + (size_t)d4.z * DH + lane * 4, a2);
    red_v4(agg + (size_t)d4.z * DH + (lane + 32) * 4, b2);
    red_v4(agg + (size_t)d4.w * DH + lane * 4, a3);
    red_v4(agg + (size_t)d4.w * DH + (lane + 32) * 4, b3);
    if (lane < 4) {
        int d = (lane == 0) ? d4.x : (lane == 1) ? d4.y : (lane == 2) ? d4.z : d4.w;
        atomicAdd(cnt + d, 1.0f);
    }
}

// ---------------- weight prep: fp16 hi, transposed [n][k] -------------------
__global__ void build_wt_h(const float* __restrict__ Wl, const float* __restrict__ Wr,
                           ushort_t* __restrict__ WtH, int KA, int K) {
    int idx = blockIdx.x * blockDim.x + threadIdx.x;
    if (idx >= 256 * K) return;
    int n = idx / K, k = idx % K;
    float w = (k < KA) ? Wl[(size_t)k * DH + n] : Wr[(size_t)(k - KA) * DH + n];
    WtH[idx] = __half_as_ushort(__float2half_rn(w));
}

// ---------------- mma.sync fp16 helpers -------------------------------------
__device__ __forceinline__ void mma16816f(float* c, uint32_t a0, uint32_t a1,
                                          uint32_t a2, uint32_t a3,
                                          uint32_t b0, uint32_t b1) {
    asm volatile(
        "mma.sync.aligned.m16n8k16.row.col.f32.f16.f16.f32 "
        "{%0,%1,%2,%3}, {%4,%5,%6,%7}, {%8,%9}, {%0,%1,%2,%3};"
        : "+f"(c[0]), "+f"(c[1]), "+f"(c[2]), "+f"(c[3])
        : "r"(a0), "r"(a1), "r"(a2), "r"(a3), "r"(b0), "r"(b1));
}
__device__ __forceinline__ void cpa16(uint32_t dst, const void* src) {
    asm volatile("cp.async.ca.shared.global [%0], [%1], 16;" :: "r"(dst), "l"(src));
}

// ---------------- 3-stage pipelined fp16 2-pass tensor-core GEMM ------------
// C = relu(A @ B^T + bias); A ~ (Ah + Al) fp16 pair, B ~ Bh fp16 only.
#define SSTR 40
template<int K, int BN>
__global__ void __launch_bounds__(256)
gemm2p(const ushort_t* __restrict__ Ah, const ushort_t* __restrict__ Al,
       const ushort_t* __restrict__ WtH,
       const float* __restrict__ bias, float* __restrict__ C)
{
    extern __shared__ ushort_t sm[];
    constexpr int ASZ = 128 * SSTR;
    constexpr int BSZ = BN * SSTR;
    constexpr int STG = 2 * ASZ + BSZ;
    constexpr int WN  = BN / 4;
    constexpr int NJ  = WN / 8;
    constexpr int NCH = K / 32;
    constexpr int BCH = BN * 4 / 256;

    const int tid  = threadIdx.x;
    const int w    = tid >> 5;
    const int lane = tid & 31;
    const int g    = lane >> 2;
    const int tg   = lane & 3;

    const int rowBase = blockIdx.x * 128;
    const int colBase = blockIdx.y * BN;
    const int mW = (w >> 2) * 64;
    const int nW = (w & 3) * WN;

    const uint32_t smB = (uint32_t)__cvta_generic_to_shared(sm);

    float acc[4][NJ][4];
#pragma unroll
    for (int i = 0; i < 4; i++)
#pragma unroll
        for (int j = 0; j < NJ; j++)
#pragma unroll
            for (int q = 0; q < 4; q++) acc[i][j][q] = 0.f;

    auto load_stage = [&](int c, int buf) {
        const int kb = c * 32;
        const uint32_t sb = smB + (uint32_t)buf * STG * 2;
#pragma unroll
        for (int t = 0; t < 2; ++t) {
            int chunk = tid + t * 256;
            int row = chunk >> 2, c4 = chunk & 3;
            uint32_t d = sb + (uint32_t)(row * SSTR + c4 * 8) * 2;
            const size_t go = (size_t)(rowBase + row) * K + kb + c4 * 8;
            cpa16(d,           Ah + go);
            cpa16(d + ASZ * 2, Al + go);
        }
#pragma unroll
        for (int t = 0; t < BCH; ++t) {
            int chunk = tid + t * 256;
            int row = chunk >> 2, c4 = chunk & 3;
            uint32_t d = sb + (uint32_t)(2 * ASZ + row * SSTR + c4 * 8) * 2;
            const size_t go = (size_t)(colBase + row) * K + kb + c4 * 8;
            cpa16(d, WtH + go);
        }
        asm volatile("cp.async.commit_group;" ::: "memory");
    };

    load_stage(0, 0);
    if (NCH > 1) load_stage(1, 1);

    for (int c = 0; c < NCH; ++c) {
        if (c + 1 < NCH) asm volatile("cp.async.wait_group 1;" ::: "memory");
        else             asm volatile("cp.async.wait_group 0;" ::: "memory");
        __syncthreads();
        if (c + 2 < NCH) load_stage(c + 2, (c + 2) % 3);

        const ushort_t* sAh = sm + (c % 3) * STG;
        const ushort_t* sAl = sAh + ASZ;
        const ushort_t* sBh = sAh + 2 * ASZ;

#pragma unroll
        for (int ks = 0; ks < 2; ++ks) {
            const int ko = ks * 16;
            uint32_t ah[4][4], al[4][4];
#pragma unroll
            for (int i = 0; i < 4; ++i) {
                int r0 = (mW + 16 * i + g) * SSTR + ko + 2 * tg;
                int r1 = r0 + 8 * SSTR;
                ah[i][0] = *(const uint32_t*)&sAh[r0];
                ah[i][1] = *(const uint32_t*)&sAh[r1];
                ah[i][2] = *(const uint32_t*)&sAh[r0 + 8];
                ah[i][3] = *(const uint32_t*)&sAh[r1 + 8];
                al[i][0] = *(const uint32_t*)&sAl[r0];
                al[i][1] = *(const uint32_t*)&sAl[r1];
                al[i][2] = *(const uint32_t*)&sAl[r0 + 8];
                al[i][3] = *(const uint32_t*)&sAl[r1 + 8];
            }
#pragma unroll
            for (int j = 0; j < NJ; ++j) {
                int nb = (nW + 8 * j + g) * SSTR + ko + 2 * tg;
                uint32_t bh0 = *(const uint32_t*)&sBh[nb];
                uint32_t bh1 = *(const uint32_t*)&sBh[nb + 8];
#pragma unroll
                for (int i = 0; i < 4; ++i) {
                    mma16816f(acc[i][j], ah[i][0], ah[i][1], ah[i][2], ah[i][3], bh0, bh1);
                    mma16816f(acc[i][j], al[i][0], al[i][1], al[i][2], al[i][3], bh0, bh1);
                }
            }
        }
    }

#pragma unroll
    for (int i = 0; i < 4; ++i) {
        int row0 = rowBase + mW + 16 * i + g;
        int row1 = row0 + 8;
#pragma unroll
        for (int j = 0; j < NJ; ++j) {
            int col = colBase + nW + 8 * j + 2 * tg;
            float2 bb = *(const float2*)(bias + col);
            float2 o0, o1;
            o0.x = fmaxf(acc[i][j][0] + bb.x, 0.f);
            o0.y = fmaxf(acc[i][j][1] + bb.y, 0.f);
            o1.x = fmaxf(acc[i][j][2] + bb.x, 0.f);
            o1.y = fmaxf(acc[i][j][3] + bb.y, 0.f);
            *(float2*)(C + (size_t)row0 * DH + col) = o0;
            *(float2*)(C + (size_t)row1 * DH + col) = o1;
        }
    }
}

// ---------------- final layer: [1024 x 47] logits + log_softmax -------------
__global__ void __launch_bounds__(64)
final_layer(const float* __restrict__ agg, const float* __restrict__ cnt,
            const float* __restrict__ h,
            const float* __restrict__ Wl, const float* __restrict__ Wr,
            const float* __restrict__ bias, float* __restrict__ out)
{
    __shared__ float sA[DH];
    __shared__ float sH[DH];
    __shared__ float sL[DOUT];
    __shared__ float sRed[2];

    int row = blockIdx.x;
    int tid = threadIdx.x;

    float scale = 1.0f / fmaxf(cnt[row], 1.0f);
    for (int i = tid; i < DH; i += 64) {
        sA[i] = agg[(size_t)row * DH + i] * scale;
        sH[i] = h[(size_t)row * DH + i];
    }
    __syncthreads();

    if (tid < DOUT) {
        float accv = bias[tid];
#pragma unroll 8
        for (int k = 0; k < DH; ++k) accv += sA[k] * Wl[k * DOUT + tid];
#pragma unroll 8
        for (int k = 0; k < DH; ++k) accv += sH[k] * Wr[k * DOUT + tid];
        sL[tid] = accv;
    }
    __syncthreads();

    if (tid < 32) {
        float v1 = (tid < DOUT)      ? sL[tid]      : -INFINITY;
        float v2 = (tid + 32 < DOUT) ? sL[tid + 32] : -INFINITY;
        float m = fmaxf(v1, v2);
#pragma unroll
        for (int off = 16; off > 0; off >>= 1)
            m = fmaxf(m, __shfl_xor_sync(0xffffffffu, m, off));
        float s = ((tid < DOUT)      ? expf(v1 - m) : 0.f)
                + ((tid + 32 < DOUT) ? expf(v2 - m) : 0.f);
#pragma unroll
        for (int off = 16; off > 0; off >>= 1)
            s += __shfl_xor_sync(0xffffffffu, s, off);
        if (tid == 0) { sRed[0] = m; sRed[1] = logf(s); }
    }
    __syncthreads();

    if (tid < DOUT)
        out[(size_t)row * DOUT + tid] = sL[tid] - sRed[0] - sRed[1];
}

// ---------------- launch ----------------------------------------------------
extern "C" void kernel_launch(void* const* d_in, const int* in_sizes, int n_in,
                              void* d_out, int out_size) {
    const float* x   = (const float*)d_in[0];
    const float* Wl0 = (const float*)d_in[1];
    const float* Wr0 = (const float*)d_in[2];
    const float* b0  = (const float*)d_in[3];
    const float* Wl1 = (const float*)d_in[4];
    const float* Wr1 = (const float*)d_in[5];
    const float* b1  = (const float*)d_in[6];
    const float* Wl2 = (const float*)d_in[7];
    const float* Wr2 = (const float*)d_in[8];
    const float* b2  = (const float*)d_in[9];
    const int* src0  = (const int*)d_in[10];
    const int* dst0  = (const int*)d_in[11];
    const int* src1  = (const int*)d_in[12];
    const int* dst1  = (const int*)d_in[13];
    const int* src2  = (const int*)d_in[14];
    const int* dst2  = (const int*)d_in[15];
    float* out = (float*)d_out;

    float *h1, *h2, *agg2, *cnt2;
    ushort_t *wt0h, *wt1h, *Ah0, *Al0, *Ah1, *Al1;
    int *icnt, *off, *cur, *part, *ssrc;
    int *icnt1, *off1, *cur1, *part1, *ssrc1;
    cudaGetSymbolAddress((void**)&h1,    g_h1);
    cudaGetSymbolAddress((void**)&h2,    g_h2);
    cudaGetSymbolAddress((void**)&agg2,  g_agg2);
    cudaGetSymbolAddress((void**)&cnt2,  g_cnt2);
    cudaGetSymbolAddress((void**)&wt0h,  g_wt0h);
    cudaGetSymbolAddress((void**)&wt1h,  g_wt1h);
    cudaGetSymbolAddress((void**)&Ah0,   g_Ah0);
    cudaGetSymbolAddress((void**)&Al0,   g_Al0);
    cudaGetSymbolAddress((void**)&Ah1,   g_Ah1);
    cudaGetSymbolAddress((void**)&Al1,   g_Al1);
    cudaGetSymbolAddress((void**)&icnt,  g_icnt);
    cudaGetSymbolAddress((void**)&off,   g_off);
    cudaGetSymbolAddress((void**)&cur,   g_cur);
    cudaGetSymbolAddress((void**)&part,  g_part);
    cudaGetSymbolAddress((void**)&ssrc,  g_ssrc);
    cudaGetSymbolAddress((void**)&icnt1, g_icnt1);
    cudaGetSymbolAddress((void**)&off1,  g_off1);
    cudaGetSymbolAddress((void**)&cur1,  g_cur1);
    cudaGetSymbolAddress((void**)&part1, g_part1);
    cudaGetSymbolAddress((void**)&ssrc1, g_ssrc1);

    const int SMEM0 = (2 * 128 * SSTR + 256 * SSTR) * 2 * 3;  // 122880
    const int SMEM1 = (2 * 128 * SSTR + 128 * SSTR) * 2 * 3;  // 92160
    cudaFuncSetAttribute(gemm2p<256, 256>, cudaFuncAttributeMaxDynamicSharedMemorySize, SMEM0);
    cudaFuncSetAttribute(gemm2p<512, 128>, cudaFuncAttributeMaxDynamicSharedMemorySize, SMEM1);

    const int NB0 = (N1c + 1023) / 1024;
    const int NB1 = (N2c + 1023) / 1024;

    // ---- layer 0 ----
    build_wt_h<<<(256 * 256 + 255) / 256, 256>>>(Wl0, Wr0, wt0h, DIN, 256);
    zero_int<<<(N1c + 255) / 256, 256>>>(icnt, N1c);
    hist_k<<<(E0c + 255) / 256, 256>>>(dst0, icnt, E0c);
    scan_block<<<NB0, 1024>>>(icnt, off, part, N1c);
    scan_partials<<<1, 1024>>>(part, NB0);
    scan_add<<<(N1c + 255) / 256, 256>>>(off, part, cur, N1c, E0c);
    sort_scatter<<<(E0c + 255) / 256, 256>>>(src0, dst0, cur, ssrc, E0c);
    agg_split<DIN, 8><<<(N1c + 7) / 8, 256>>>(ssrc, off, x, x, Ah0, Al0, N1c);
    gemm2p<256, 256><<<dim3(N1c / 128, 1), 256, SMEM0>>>(Ah0, Al0, wt0h, b0, h1);

    // ---- layer 1 ----
    build_wt_h<<<(256 * 512 + 255) / 256, 256>>>(Wl1, Wr1, wt1h, DH, 512);
    zero_int<<<(N2c + 255) / 256, 256>>>(icnt1, N2c);
    hist_k<<<(E1c + 255) / 256, 256>>>(dst1, icnt1, E1c);
    scan_block<<<NB1, 1024>>>(icnt1, off1, part1, N2c);
    scan_partials<<<1, 1024>>>(part1, NB1);
    scan_add<<<(N2c + 255) / 256, 256>>>(off1, part1, cur1, N2c, E1c);
    sort_scatter<<<(E1c + 255) / 256, 256>>>(src1, dst1, cur1, ssrc1, E1c);
    agg_split<DH, 4><<<(N2c + 7) / 8, 256>>>(ssrc1, off1, h1, h1, Ah1, Al1, N2c);
    gemm2p<512, 128><<<dim3(N2c / 128, 2), 256, SMEM1>>>(Ah1, Al1, wt1h, b1, h2);

    // ---- layer 2 ----
    zero_agg<<<(N3c * (DH/4) + 255) / 256, 256>>>((float4*)agg2, cnt2, N3c * (DH/4), N3c);
    scatter_h4<<<E2c / 32, 256>>>(src2, dst2, h2, agg2, cnt2, E2c);
    final_layer<<<N3c, 64>>>(agg2, cnt2, h2, Wl2, Wr2, b2, out);
}